// round 12
// baseline (speedup 1.0000x reference)
#include <cuda_runtime.h>
#include <cuda_bf16.h>
#include <math.h>
#include <stdint.h>

#define BB    2
#define TT    2048
#define CC    2048
#define HH    16
#define DD    128
#define MM    (BB*TT)          // 4096 token rows
#define BH    (BB*HH)          // 32

#define KC    32               // GEMM K per chunk
#define NCHUNK (CC/KC)         // 64

// GEMM smem per stage: Ah[256][40] 20480 | Al 20480 | Bh[128][40] 10240 | Bl 10240
#define A_OFF_L 20480
#define B_OFF_H 40960
#define B_OFF_L 51200
#define STAGE_B 61440
#define GEMM_SMEM (2*STAGE_B)  // 122880, 1 CTA/SM, 512 threads

#define NGEMM_CTAS 148
#define NTILES_QKV 768         // 3 x (16 m-tiles of 256) x (16 n-tiles of 128)
#define NTILES_OUT 256         // 16 x 16

// ---- static device scratch (allocation-free) ----
__device__ __nv_bfloat16 g_xh[MM*CC],  g_xl[MM*CC];     // pre-split input
__device__ __nv_bfloat16 g_wqh[CC*CC], g_wql[CC*CC];
__device__ __nv_bfloat16 g_wkh[CC*CC], g_wkl[CC*CC];
__device__ __nv_bfloat16 g_wvh[CC*CC], g_wvl[CC*CC];
__device__ __nv_bfloat16 g_woh[CC*CC], g_wol[CC*CC];
__device__ __nv_bfloat16 g_qh[BH*TT*DD], g_ql[BH*TT*DD];   // roped q  [bh][t][d]
__device__ __nv_bfloat16 g_kh[BH*TT*DD], g_kl[BH*TT*DD];   // roped k  [bh][t][d]
__device__ __nv_bfloat16 g_vth[BH*DD*TT], g_vtl[BH*DD*TT]; // v transposed [bh][d][t]
__device__ __nv_bfloat16 g_ah[MM*CC],  g_al[MM*CC];        // attn out rows [B,T,C]

// ============================================================
// helpers
// ============================================================
__device__ __forceinline__ uint32_t smem_u32(const void* p) {
    uint32_t a;
    asm("{ .reg .u64 t; cvta.to.shared.u64 t, %1; cvt.u32.u64 %0, t; }" : "=r"(a) : "l"(p));
    return a;
}
__device__ __forceinline__ void mma_bf16(float* d, const uint32_t* a, const uint32_t* b) {
    asm volatile(
        "mma.sync.aligned.m16n8k16.row.col.f32.bf16.bf16.f32 "
        "{%0,%1,%2,%3}, {%4,%5,%6,%7}, {%8,%9}, {%0,%1,%2,%3};"
        : "+f"(d[0]), "+f"(d[1]), "+f"(d[2]), "+f"(d[3])
        : "r"(a[0]), "r"(a[1]), "r"(a[2]), "r"(a[3]), "r"(b[0]), "r"(b[1]));
}
__device__ __forceinline__ void ldsm4(uint32_t* r, uint32_t addr) {
    asm volatile("ldmatrix.sync.aligned.m8n8.x4.shared.b16 {%0,%1,%2,%3}, [%4];"
        : "=r"(r[0]), "=r"(r[1]), "=r"(r[2]), "=r"(r[3]) : "r"(addr));
}
#define CP_ASYNC16(dst, src) \
    asm volatile("cp.async.cg.shared.global [%0], [%1], 16;" :: "r"(dst), "l"(src))
#define CP_COMMIT() asm volatile("cp.async.commit_group;" ::: "memory")
#define CP_WAIT0()  asm volatile("cp.async.wait_group 0;" ::: "memory")
#define CP_WAIT1()  asm volatile("cp.async.wait_group 1;" ::: "memory")

__device__ __forceinline__ void split2(float a, float b, uint32_t& hi, uint32_t& lo) {
    __nv_bfloat16 ha = __float2bfloat16_rn(a);
    __nv_bfloat16 hb = __float2bfloat16_rn(b);
    float la = a - __bfloat162float(ha);
    float lb = b - __bfloat162float(hb);
    __nv_bfloat162 h; h.x = ha; h.y = hb;
    hi = *(uint32_t*)&h;
    __nv_bfloat162 l = __floats2bfloat162_rn(la, lb);
    lo = *(uint32_t*)&l;
}

// ============================================================
// fused fp32 -> bf16 hi/lo splitter (x + 4 weights, one launch)
// segments of 1M float4 groups: [x(2), Wq, Wk, Wv, Wo]
// ============================================================
__global__ __launch_bounds__(256) void split_all(
    const float* __restrict__ x,  const float* __restrict__ Wq,
    const float* __restrict__ Wk, const float* __restrict__ Wv,
    const float* __restrict__ Wo)
{
    int i = blockIdx.x * 256 + threadIdx.x;   // 0 .. 6291455
    int seg = i >> 20;
    const float* src;
    __nv_bfloat16 *h, *l;
    int off;
    if (seg < 2)      { src = x;  h = g_xh;  l = g_xl;  off = i; }
    else if (seg == 2){ src = Wq; h = g_wqh; l = g_wql; off = i - (2 << 20); }
    else if (seg == 3){ src = Wk; h = g_wkh; l = g_wkl; off = i - (3 << 20); }
    else if (seg == 4){ src = Wv; h = g_wvh; l = g_wvl; off = i - (4 << 20); }
    else              { src = Wo; h = g_woh; l = g_wol; off = i - (5 << 20); }
    float4 v = ((const float4*)src)[off];
    uint32_t h0, l0, h1, l1;
    split2(v.x, v.y, h0, l0);
    split2(v.z, v.w, h1, l1);
    uint2 hh; hh.x = h0; hh.y = h1;
    uint2 ll; ll.x = l0; ll.y = l1;
    ((uint2*)h)[off] = hh;
    ((uint2*)l)[off] = ll;
}

// ============================================================
// bf16x3 GEMM mainloop v5: 256x128 tile, 512 threads (16 warps,
// 4x4), cp.async 2-stage, ldmatrix. 1 CTA/SM.
// ============================================================
__device__ __forceinline__ void mma_mainloop5(
    const __nv_bfloat16* __restrict__ Ahg, const __nv_bfloat16* __restrict__ Alg,
    const __nv_bfloat16* __restrict__ Bhg, const __nv_bfloat16* __restrict__ Blg,
    int m0, int n0, char* gsm, float acc[4][4][4])
{
    const int tid  = threadIdx.x;
    const int wid  = tid >> 5;
    const int lane = tid & 31;
    const int wm   = wid >> 2;        // 0..3 (64-row bands)
    const int wn   = wid & 3;         // 0..3 (32-col bands)
    const int lr16 = lane & 15;
    const int lhalf = lane >> 4;

    const uint32_t sbase = smem_u32(gsm);
    const int lrow = tid >> 2;        // 0..127
    const int lseg = (tid & 3) * 8;   // 0,8,16,24 bf16

    auto issue = [&](int ic, int s) {
        uint32_t sb = sbase + s * STAGE_B;
        size_t kof = (size_t)ic * KC;
#pragma unroll
        for (int it = 0; it < 2; it++) {
            int row = lrow + it * 128;                       // 0..255
            uint32_t so = (uint32_t)(row * 40 + lseg) * 2;
            size_t ga = (size_t)(m0 + row) * CC + kof + lseg;
            CP_ASYNC16(sb + so,           Ahg + ga);
            CP_ASYNC16(sb + A_OFF_L + so, Alg + ga);
        }
        {
            uint32_t so = (uint32_t)(lrow * 40 + lseg) * 2;
            size_t gb = (size_t)(n0 + lrow) * CC + kof + lseg;
            CP_ASYNC16(sb + B_OFF_H + so, Bhg + gb);
            CP_ASYNC16(sb + B_OFF_L + so, Blg + gb);
        }
        CP_COMMIT();
    };

    issue(0, 0);

    for (int ic = 0; ic < NCHUNK; ic++) {
        CP_WAIT0();
        __syncthreads();
        if (ic + 1 < NCHUNK) issue(ic + 1, (ic + 1) & 1);

        const uint32_t st = sbase + (ic & 1) * STAGE_B;
#pragma unroll
        for (int kk = 0; kk < 2; kk++) {
            const uint32_t colb = (uint32_t)(kk * 16 + lhalf * 8) * 2;
            uint32_t ah[4][4], al[4][4];
#pragma unroll
            for (int i = 0; i < 4; i++) {
                uint32_t ra = st + (uint32_t)((wm * 64 + i * 16 + lr16) * 40) * 2 + colb;
                ldsm4(ah[i], ra);
                ldsm4(al[i], ra + A_OFF_L);
            }
            uint32_t bh[2][4], bl[2][4];
#pragma unroll
            for (int jp = 0; jp < 2; jp++) {
                uint32_t rb = st + B_OFF_H + (uint32_t)((wn * 32 + jp * 16 + lr16) * 40) * 2 + colb;
                ldsm4(bh[jp], rb);
                ldsm4(bl[jp], rb + 10240);
            }
#pragma unroll
            for (int i = 0; i < 4; i++)
#pragma unroll
                for (int j = 0; j < 4; j++) {
                    const int jp = j >> 1, jo = j & 1;
                    uint32_t bj_h[2] = { bh[jp][jo], bh[jp][jo + 2] };
                    uint32_t bj_l[2] = { bl[jp][jo], bl[jp][jo + 2] };
                    mma_bf16(acc[i][j], ah[i], bj_h);
                    mma_bf16(acc[i][j], ah[i], bj_l);
                    mma_bf16(acc[i][j], al[i], bj_h);
                }
        }
    }
}

// ============================================================
// Persistent QKV projection with fused RoPE/split + V transpose.
// 256-row tiles: epilogue in two 128-row halves via smem.
// ============================================================
__global__ __launch_bounds__(512, 1) void mma_gemm_qkv()
{
    extern __shared__ char gsm[];
    float* eps = (float*)gsm;             // [128][131] fp32 (67072 B)
    const int tid = threadIdx.x, wid = tid >> 5, lane = tid & 31;
    const int wm = wid >> 2, wn = wid & 3, g = lane >> 2, kc = lane & 3;

    const int ri = tid & 63;              // rope pair index
    const float rope_inv = powf(10000.0f, -(float)(2 * ri) / 128.0f);

    for (int tile = blockIdx.x; tile < NTILES_QKV; tile += gridDim.x) {
        const int z = tile >> 8;          // 0,1,2
        const int rem = tile & 255;
        const int n0 = (rem & 15) * 128;
        const int m0 = (rem >> 4) * 256;
        const __nv_bfloat16* Bhg = (z == 0) ? g_wqh : (z == 1) ? g_wkh : g_wvh;
        const __nv_bfloat16* Blg = (z == 0) ? g_wql : (z == 1) ? g_wkl : g_wvl;

        float acc[4][4][4];
#pragma unroll
        for (int i = 0; i < 4; i++)
#pragma unroll
            for (int j = 0; j < 4; j++)
#pragma unroll
                for (int r = 0; r < 4; r++) acc[i][j][r] = 0.f;

        mma_mainloop5(g_xh, g_xl, Bhg, Blg, m0, n0, gsm, acc);

        const int h = n0 >> 7;
#pragma unroll
        for (int rep = 0; rep < 2; rep++) {
            __syncthreads();              // stage reads (rep0) / prev scatter done
            if ((wm >> 1) == rep) {
                const int rb = (wm & 1) * 64;
#pragma unroll
                for (int i = 0; i < 4; i++) {
                    int r0 = rb + i * 16 + g, r1 = r0 + 8;
#pragma unroll
                    for (int j = 0; j < 4; j++) {
                        int c = wn * 32 + j * 8 + kc * 2;
                        eps[r0 * 131 + c]     = acc[i][j][0];
                        eps[r0 * 131 + c + 1] = acc[i][j][1];
                        eps[r1 * 131 + c]     = acc[i][j][2];
                        eps[r1 * 131 + c + 1] = acc[i][j][3];
                    }
                }
            }
            __syncthreads();

            const int mrow = m0 + rep * 128;
            const int b = mrow >> 11;
            if (z < 2) {
                __nv_bfloat16* dh = ((z == 0) ? g_qh : g_kh) + (size_t)(b * HH + h) * TT * DD;
                __nv_bfloat16* dl = ((z == 0) ? g_ql : g_kl) + (size_t)(b * HH + h) * TT * DD;
                const int rg = tid >> 6;  // 0..7, 16 rows each
#pragma unroll 4
                for (int rr = 0; rr < 16; rr++) {
                    int r = rg * 16 + rr;
                    int t = (mrow + r) & 2047;
                    float ang = (float)t * rope_inv;
                    float s_, c_;
                    sincosf(ang, &s_, &c_);
                    float x1 = eps[r * 131 + ri];
                    float x2 = eps[r * 131 + ri + 64];
                    float v1 = x1 * c_ - x2 * s_;
                    float v2 = x2 * c_ + x1 * s_;
                    size_t base = (size_t)t * DD + ri;
                    __nv_bfloat16 h1 = __float2bfloat16_rn(v1);
                    dh[base] = h1;
                    dl[base] = __float2bfloat16_rn(v1 - __bfloat162float(h1));
                    __nv_bfloat16 h2 = __float2bfloat16_rn(v2);
                    dh[base + 64] = h2;
                    dl[base + 64] = __float2bfloat16_rn(v2 - __bfloat162float(h2));
                }
            } else {
                __nv_bfloat16* dh = g_vth + (size_t)(b * HH + h) * DD * TT;
                __nv_bfloat16* dl = g_vtl + (size_t)(b * HH + h) * DD * TT;
                const int d  = tid & 127;
                const int th = (tid >> 7) * 32;
                const int trow = mrow & 2047;
#pragma unroll
                for (int u = 0; u < 32; u += 8) {
                    __nv_bfloat16 hv[8], lv[8];
#pragma unroll
                    for (int w = 0; w < 8; w++) {
                        float v = eps[(th + u + w) * 131 + d];
                        __nv_bfloat16 hh = __float2bfloat16_rn(v);
                        hv[w] = hh;
                        lv[w] = __float2bfloat16_rn(v - __bfloat162float(hh));
                    }
                    *(uint4*)&dh[(size_t)d * TT + trow + th + u] = *(uint4*)hv;
                    *(uint4*)&dl[(size_t)d * TT + trow + th + u] = *(uint4*)lv;
                }
            }
        }
        __syncthreads();                  // eps free before next tile's cp.async
    }
}

// ============================================================
// Persistent output projection: out = attn(hi/lo) @ Wo^T -> fp32
// ============================================================
__global__ __launch_bounds__(512, 1) void mma_gemm_out(float* __restrict__ out)
{
    extern __shared__ char gsm[];
    const int tid = threadIdx.x, wid = tid >> 5, lane = tid & 31;
    const int wm = wid >> 2, wn = wid & 3, g = lane >> 2, kc = lane & 3;

    for (int tile = blockIdx.x; tile < NTILES_OUT; tile += gridDim.x) {
        const int n0 = (tile & 15) * 128;
        const int m0 = (tile >> 4) * 256;

        float acc[4][4][4];
#pragma unroll
        for (int i = 0; i < 4; i++)
#pragma unroll
            for (int j = 0; j < 4; j++)
#pragma unroll
                for (int r = 0; r < 4; r++) acc[i][j][r] = 0.f;

        mma_mainloop5(g_ah, g_al, g_woh, g_wol, m0, n0, gsm, acc);

#pragma unroll
        for (int i = 0; i < 4; i++) {
            int m = m0 + wm * 64 + i * 16 + g;
            float* d0 = out + (size_t)m * CC + n0;
            float* d1 = out + (size_t)(m + 8) * CC + n0;
#pragma unroll
            for (int j = 0; j < 4; j++) {
                int c = wn * 32 + j * 8 + kc * 2;
                d0[c]     = acc[i][j][0];
                d0[c + 1] = acc[i][j][1];
                d1[c]     = acc[i][j][2];
                d1[c + 1] = acc[i][j][3];
            }
        }
        __syncthreads();   // stage reads done before next tile's issue
    }
}

// ============================================================
// Tensor-core flash attention, cp.async double-buffered K/V.
// Linear grid, descending-cost schedule.
// ============================================================
#define AQH 0
#define AQL 17408
#define ASTG 34816
#define ASTRIDE 35840
#define ATT_SMEM_BF16 (ASTG + 2*ASTRIDE)   // 106496
#define ATT_SMEM_BYTES (ATT_SMEM_BF16 * 2) // 212992

__global__ __launch_bounds__(256) void attn_mma_kernel()
{
    extern __shared__ __nv_bfloat16 sm[];
    __nv_bfloat16* sQh = sm + AQH;   // [128][136]
    __nv_bfloat16* sQl = sm + AQL;

    const int tid = threadIdx.x;
    const int wid = tid >> 5;
    const int lane = tid & 31;
    const int g  = lane >> 2;
    const int kc = lane & 3;
    const int bid = blockIdx.x;
    const int qt = (TT / 128 - 1) - (bid >> 5);   // big tiles first
    const int bh = bid & 31;
    const int q0 = qt * 128;

    const __nv_bfloat16* Qhg = g_qh + ((size_t)bh * TT + q0) * DD;
    const __nv_bfloat16* Qlg = g_ql + ((size_t)bh * TT + q0) * DD;
    const __nv_bfloat16* Khg = g_kh + (size_t)bh * TT * DD;
    const __nv_bfloat16* Klg = g_kl + (size_t)bh * TT * DD;
    const __nv_bfloat16* Vhg = g_vth + (size_t)bh * DD * TT;
    const __nv_bfloat16* Vlg = g_vtl + (size_t)bh * DD * TT;

    const uint32_t smb = smem_u32(sm);

    // load Q tile (128 x 128)
    for (int f = tid; f < 2048; f += 256) {
        int row = f >> 4, seg = (f & 15) * 8;
        *(uint4*)&sQh[row * 136 + seg] = *(const uint4*)&Qhg[row * DD + seg];
        *(uint4*)&sQl[row * 136 + seg] = *(const uint4*)&Qlg[row * DD + seg];
    }

    const uint32_t* q32h = (const uint32_t*)sQh;
    const uint32_t* q32l = (const uint32_t*)sQl;

    auto issue_kv = [&](int kt, int s) {
        const int k0 = kt * 64;
        uint32_t stb = smb + (uint32_t)(ASTG + s * ASTRIDE) * 2;
#pragma unroll
        for (int it = 0; it < 4; it++) {
            int f = tid + it * 256;
            int row = f >> 4, seg = (f & 15) * 8;
            uint32_t so = (uint32_t)(row * 136 + seg) * 2;
            CP_ASYNC16(stb + so,            Khg + (size_t)(k0 + row) * DD + seg);
            CP_ASYNC16(stb + 8704*2 + so,   Klg + (size_t)(k0 + row) * DD + seg);
        }
#pragma unroll
        for (int it = 0; it < 4; it++) {
            int f = tid + it * 256;
            int row = f >> 3, seg = (f & 7) * 8;
            uint32_t so = (uint32_t)(row * 72 + seg) * 2;
            CP_ASYNC16(stb + 17408*2 + so,  Vhg + (size_t)row * TT + k0 + seg);
            CP_ASYNC16(stb + 26624*2 + so,  Vlg + (size_t)row * TT + k0 + seg);
        }
        CP_COMMIT();
    };

    float o[16][4];
#pragma unroll
    for (int n = 0; n < 16; n++)
#pragma unroll
        for (int e = 0; e < 4; e++) o[n][e] = 0.f;
    float m0 = -INFINITY, m1 = -INFINITY, l0 = 0.f, l1 = 0.f;
    const float scale = 0.088388347648318447f;   // 1/sqrt(128)
    const int rq = wid * 16;

    const int nkt = 2 * qt + 2;     // cover keys [0, q0+128)
    issue_kv(0, 0);
    for (int kt = 0; kt < nkt; kt++) {
        const int k0 = kt * 64;
        if (kt) __syncthreads();                 // stage (kt+1)&1 free
        if (kt + 1 < nkt) { issue_kv(kt + 1, (kt + 1) & 1); CP_WAIT1(); }
        else              { CP_WAIT0(); }
        __syncthreads();                          // tile kt visible (and Q on kt==0)

        const uint32_t* k32h = (const uint32_t*)(sm + ASTG + (kt & 1) * ASTRIDE);
        const uint32_t* k32l = k32h + 4352;
        const uint32_t* v32h = k32h + 8704;
        const uint32_t* v32l = k32h + 13312;

        // ---- S = Q K^T (bf16x3) ----
        float s[8][4];
#pragma unroll
        for (int j = 0; j < 8; j++)
#pragma unroll
            for (int e = 0; e < 4; e++) s[j][e] = 0.f;

#pragma unroll
        for (int ks = 0; ks < 8; ks++) {
            const int c = ks * 8 + kc;
            uint32_t ah[4], al[4];
            ah[0] = q32h[(rq + g) * 68 + c];
            ah[1] = q32h[(rq + g + 8) * 68 + c];
            ah[2] = q32h[(rq + g) * 68 + c + 4];
            ah[3] = q32h[(rq + g + 8) * 68 + c + 4];
            al[0] = q32l[(rq + g) * 68 + c];
            al[1] = q32l[(rq + g + 8) * 68 + c];
            al[2] = q32l[(rq + g) * 68 + c + 4];
            al[3] = q32l[(rq + g + 8) * 68 + c + 4];
#pragma unroll
            for (int j = 0; j < 8; j++) {
                int rn = (j * 8 + g) * 68 + c;
                uint32_t kb[2], kl2[2];
                kb[0]  = k32h[rn]; kb[1]  = k32h[rn + 4];
                kl2[0] = k32l[rn]; kl2[1] = k32l[rn + 4];
                mma_bf16(s[j], ah, kb);
                mma_bf16(s[j], ah, kl2);
                mma_bf16(s[j], al, kb);
            }
        }

        // scale + causal mask (only on the two diagonal tiles)
        const int row0 = q0 + rq + g;
        const int row1 = row0 + 8;
#pragma unroll
        for (int j = 0; j < 8; j++)
#pragma unroll
            for (int e = 0; e < 4; e++) s[j][e] *= scale;
        if (kt >= 2 * qt) {
#pragma unroll
            for (int j = 0; j < 8; j++) {
                int cb = k0 + j * 8 + kc * 2;
                if (cb     > row0) s[j][0] = -INFINITY;
                if (cb + 1 > row0) s[j][1] = -INFINITY;
                if (cb     > row1) s[j][2] = -INFINITY;
                if (cb + 1 > row1) s[j][3] = -INFINITY;
            }
        }

        // ---- online softmax ----
        float mx0 = -INFINITY, mx1 = -INFINITY;
#pragma unroll
        for (int j = 0; j < 8; j++) {
            mx0 = fmaxf(mx0, fmaxf(s[j][0], s[j][1]));
            mx1 = fmaxf(mx1, fmaxf(s[j][2], s[j][3]));
        }
        mx0 = fmaxf(mx0, __shfl_xor_sync(0xffffffffu, mx0, 1));
        mx0 = fmaxf(mx0, __shfl_xor_sync(0xffffffffu, mx0, 2));
        mx1 = fmaxf(mx1, __shfl_xor_sync(0xffffffffu, mx1, 1));
        mx1 = fmaxf(mx1, __shfl_xor_sync(0xffffffffu, mx1, 2));
        float mn0 = fmaxf(m0, mx0), mn1 = fmaxf(m1, mx1);
        float r0 = __expf(m0 - mn0), r1 = __expf(m1 - mn1);
        float sum0 = 0.f, sum1 = 0.f;
#pragma unroll
        for (int j = 0; j < 8; j++) {
            s[j][0] = __expf(s[j][0] - mn0); sum0 += s[j][0];
            s[j][1] = __expf(s[j][1] - mn0); sum0 += s[j][1];
            s[j][2] = __expf(s[j][2] - mn1); sum1 += s[j][2];
            s[j][3] = __expf(s[j][3] - mn1); sum1 += s[j][3];
        }
        sum0 += __shfl_xor_sync(0xffffffffu, sum0, 1);
        sum0 += __shfl_xor_sync(0xffffffffu, sum0, 2);
        sum1 += __shfl_xor_sync(0xffffffffu, sum1, 1);
        sum1 += __shfl_xor_sync(0xffffffffu, sum1, 2);
        l0 = l0 * r0 + sum0;  m0 = mn0;
        l1 = l1 * r1 + sum1;  m1 = mn1;
#pragma unroll
        for (int n = 0; n < 16; n++) {
            o[n][0] *= r0; o[n][1] *= r0;
            o[n][2] *= r1; o[n][3] *= r1;
        }

        // ---- O += P V (bf16x3) ----
#pragma unroll
        for (int ks2 = 0; ks2 < 4; ks2++) {
            const int j0 = ks2 * 2, j1 = j0 + 1;
            uint32_t ph[4], pl[4];
            split2(s[j0][0], s[j0][1], ph[0], pl[0]);
            split2(s[j0][2], s[j0][3], ph[1], pl[1]);
            split2(s[j1][0], s[j1][1], ph[2], pl[2]);
            split2(s[j1][2], s[j1][3], ph[3], pl[3]);
            const int c = ks2 * 8 + kc;
#pragma unroll
            for (int nd = 0; nd < 16; nd++) {
                int rv = (nd * 8 + g) * 36 + c;
                uint32_t vb[2], vl2[2];
                vb[0]  = v32h[rv]; vb[1]  = v32h[rv + 4];
                vl2[0] = v32l[rv]; vl2[1] = v32l[rv + 4];
                mma_bf16(o[nd], ph, vb);
                mma_bf16(o[nd], ph, vl2);
                mma_bf16(o[nd], pl, vb);
            }
        }
    }

    // ---- epilogue: normalize + split -> g_ah / g_al [B,T,C] ----
    float i0 = 1.f / l0, i1 = 1.f / l1;
    const int b = bh >> 4, h = bh & 15;
    const int t0r = q0 + rq + g;
    __nv_bfloat16* ah0 = g_ah + ((size_t)(b * TT + t0r)) * CC + h * DD;
    __nv_bfloat16* al0 = g_al + ((size_t)(b * TT + t0r)) * CC + h * DD;
    __nv_bfloat16* ah1 = g_ah + ((size_t)(b * TT + t0r + 8)) * CC + h * DD;
    __nv_bfloat16* al1 = g_al + ((size_t)(b * TT + t0r + 8)) * CC + h * DD;
#pragma unroll
    for (int nd = 0; nd < 16; nd++) {
        int cc2 = nd * 8 + kc * 2;
        uint32_t hh, ll;
        split2(o[nd][0] * i0, o[nd][1] * i0, hh, ll);
        *(uint32_t*)&ah0[cc2] = hh;
        *(uint32_t*)&al0[cc2] = ll;
        split2(o[nd][2] * i1, o[nd][3] * i1, hh, ll);
        *(uint32_t*)&ah1[cc2] = hh;
        *(uint32_t*)&al1[cc2] = ll;
    }
}

// ============================================================
extern "C" void kernel_launch(void* const* d_in, const int* in_sizes, int n_in,
                              void* d_out, int out_size)
{
    const float* x  = (const float*)d_in[0];
    const float* Wq = (const float*)d_in[1];
    const float* Wk = (const float*)d_in[2];
    const float* Wv = (const float*)d_in[3];
    const float* Wo = (const float*)d_in[4];
    float* out = (float*)d_out;

    cudaFuncSetAttribute(attn_mma_kernel, cudaFuncAttributeMaxDynamicSharedMemorySize,
                         ATT_SMEM_BYTES);
    cudaFuncSetAttribute(mma_gemm_qkv, cudaFuncAttributeMaxDynamicSharedMemorySize,
                         GEMM_SMEM);
    cudaFuncSetAttribute(mma_gemm_out, cudaFuncAttributeMaxDynamicSharedMemorySize,
                         GEMM_SMEM);

    // 0) fused pre-split of x + all weights (one launch)
    split_all<<<24576, 256>>>(x, Wq, Wk, Wv, Wo);

    // 1) persistent QKV projections (256x128 tiles) + fused RoPE/V-transpose
    mma_gemm_qkv<<<NGEMM_CTAS, 512, GEMM_SMEM>>>();

    // 2) tensor-core causal flash attention (descending-cost schedule)
    attn_mma_kernel<<<(TT / 128) * BH, 256, ATT_SMEM_BYTES>>>();

    // 3) persistent output projection (256x128 tiles) -> fp32 out
    mma_gemm_out<<<NGEMM_CTAS, 512, GEMM_SMEM>>>(out);
}

// round 13
// speedup vs baseline: 1.0434x; 1.0434x over previous
#include <cuda_runtime.h>
#include <cuda_bf16.h>
#include <math.h>
#include <stdint.h>

#define BB    2
#define TT    2048
#define CC    2048
#define HH    16
#define DD    128
#define MM    (BB*TT)          // 4096 token rows
#define BH    (BB*HH)          // 32

#define KC    32               // GEMM K per chunk
#define NCHUNK (CC/KC)         // 64

// GEMM smem: per stage 4 arrays of [128][40] bf16 = 10240 B each
#define ARR_B   10240
#define STAGE_B (4*ARR_B)      // 40960
#define GEMM_SMEM2 (2*STAGE_B) // 81920 -> 2 CTAs/SM

#define NGEMM_CTAS 296         // 2 per SM
#define NTILES_QKV 1536        // 3 weights x (32 m-tiles x 16 n-tiles)
#define NTILES_OUT 512

// ---- static device scratch (allocation-free) ----
__device__ __nv_bfloat16 g_xh[MM*CC],  g_xl[MM*CC];     // pre-split input
__device__ __nv_bfloat16 g_wqh[CC*CC], g_wql[CC*CC];
__device__ __nv_bfloat16 g_wkh[CC*CC], g_wkl[CC*CC];
__device__ __nv_bfloat16 g_wvh[CC*CC], g_wvl[CC*CC];
__device__ __nv_bfloat16 g_woh[CC*CC], g_wol[CC*CC];
__device__ __nv_bfloat16 g_qh[BH*TT*DD], g_ql[BH*TT*DD];   // roped q  [bh][t][d]
__device__ __nv_bfloat16 g_kh[BH*TT*DD], g_kl[BH*TT*DD];   // roped k  [bh][t][d]
__device__ __nv_bfloat16 g_vth[BH*DD*TT], g_vtl[BH*DD*TT]; // v transposed [bh][d][t]
__device__ __nv_bfloat16 g_ah[MM*CC],  g_al[MM*CC];        // attn out rows [B,T,C]

// ============================================================
// helpers
// ============================================================
__device__ __forceinline__ uint32_t smem_u32(const void* p) {
    uint32_t a;
    asm("{ .reg .u64 t; cvta.to.shared.u64 t, %1; cvt.u32.u64 %0, t; }" : "=r"(a) : "l"(p));
    return a;
}
__device__ __forceinline__ void mma_bf16(float* d, const uint32_t* a, const uint32_t* b) {
    asm volatile(
        "mma.sync.aligned.m16n8k16.row.col.f32.bf16.bf16.f32 "
        "{%0,%1,%2,%3}, {%4,%5,%6,%7}, {%8,%9}, {%0,%1,%2,%3};"
        : "+f"(d[0]), "+f"(d[1]), "+f"(d[2]), "+f"(d[3])
        : "r"(a[0]), "r"(a[1]), "r"(a[2]), "r"(a[3]), "r"(b[0]), "r"(b[1]));
}
__device__ __forceinline__ void ldsm4(uint32_t* r, uint32_t addr) {
    asm volatile("ldmatrix.sync.aligned.m8n8.x4.shared.b16 {%0,%1,%2,%3}, [%4];"
        : "=r"(r[0]), "=r"(r[1]), "=r"(r[2]), "=r"(r[3]) : "r"(addr));
}
#define CP_ASYNC16(dst, src) \
    asm volatile("cp.async.cg.shared.global [%0], [%1], 16;" :: "r"(dst), "l"(src))
#define CP_COMMIT() asm volatile("cp.async.commit_group;" ::: "memory")
#define CP_WAIT0()  asm volatile("cp.async.wait_group 0;" ::: "memory")
#define CP_WAIT1()  asm volatile("cp.async.wait_group 1;" ::: "memory")

__device__ __forceinline__ void split2(float a, float b, uint32_t& hi, uint32_t& lo) {
    __nv_bfloat16 ha = __float2bfloat16_rn(a);
    __nv_bfloat16 hb = __float2bfloat16_rn(b);
    float la = a - __bfloat162float(ha);
    float lb = b - __bfloat162float(hb);
    __nv_bfloat162 h; h.x = ha; h.y = hb;
    hi = *(uint32_t*)&h;
    __nv_bfloat162 l = __floats2bfloat162_rn(la, lb);
    lo = *(uint32_t*)&l;
}

// ============================================================
// fused fp32 -> bf16 hi/lo splitter (x + 4 weights, one launch)
// segments of 1M float4 groups: [x(2), Wq, Wk, Wv, Wo]
// ============================================================
__global__ __launch_bounds__(256) void split_all(
    const float* __restrict__ x,  const float* __restrict__ Wq,
    const float* __restrict__ Wk, const float* __restrict__ Wv,
    const float* __restrict__ Wo)
{
    int i = blockIdx.x * 256 + threadIdx.x;   // 0 .. 6291455
    int seg = i >> 20;
    const float* src;
    __nv_bfloat16 *h, *l;
    int off;
    if (seg < 2)      { src = x;  h = g_xh;  l = g_xl;  off = i; }
    else if (seg == 2){ src = Wq; h = g_wqh; l = g_wql; off = i - (2 << 20); }
    else if (seg == 3){ src = Wk; h = g_wkh; l = g_wkl; off = i - (3 << 20); }
    else if (seg == 4){ src = Wv; h = g_wvh; l = g_wvl; off = i - (4 << 20); }
    else              { src = Wo; h = g_woh; l = g_wol; off = i - (5 << 20); }
    float4 v = ((const float4*)src)[off];
    uint32_t h0, l0, h1, l1;
    split2(v.x, v.y, h0, l0);
    split2(v.z, v.w, h1, l1);
    uint2 hh; hh.x = h0; hh.y = h1;
    uint2 ll; ll.x = l0; ll.y = l1;
    ((uint2*)h)[off] = hh;
    ((uint2*)l)[off] = ll;
}

// ============================================================
// bf16x3 GEMM mainloop (R9-proven): 128x128 tile, 256 threads
// (8 warps 2x4), cp.async 2-stage, ldmatrix, 2 CTAs/SM.
// ============================================================
__device__ __forceinline__ void mma_mainloop4(
    const __nv_bfloat16* __restrict__ Ahg, const __nv_bfloat16* __restrict__ Alg,
    const __nv_bfloat16* __restrict__ Bhg, const __nv_bfloat16* __restrict__ Blg,
    int m0, int n0, char* gsm, float acc[4][4][4])
{
    const int tid  = threadIdx.x;
    const int wid  = tid >> 5;
    const int lane = tid & 31;
    const int wm   = wid >> 2;
    const int wn   = wid & 3;
    const int lr16 = lane & 15;
    const int lhalf = lane >> 4;

    const uint32_t sbase = smem_u32(gsm);

    const int lrow = tid >> 2;            // 0..63
    const int lseg = (tid & 3) * 8;       // 0,8,16,24 bf16

    auto issue = [&](int ic, int s) {
        uint32_t sb = sbase + s * STAGE_B;
        size_t kof = (size_t)ic * KC;
#pragma unroll
        for (int it = 0; it < 2; it++) {
            int row = lrow + it * 64;
            uint32_t so = (uint32_t)(row * 40 + lseg) * 2;
            size_t ga = (size_t)(m0 + row) * CC + kof + lseg;
            size_t gb = (size_t)(n0 + row) * CC + kof + lseg;
            CP_ASYNC16(sb + so,             Ahg + ga);
            CP_ASYNC16(sb + ARR_B + so,     Alg + ga);
            CP_ASYNC16(sb + 2*ARR_B + so,   Bhg + gb);
            CP_ASYNC16(sb + 3*ARR_B + so,   Blg + gb);
        }
        CP_COMMIT();
    };

    issue(0, 0);

    for (int ic = 0; ic < NCHUNK; ic++) {
        CP_WAIT0();            // stage ic ready (only pending group)
        __syncthreads();       // all warps done with the other stage
        if (ic + 1 < NCHUNK) issue(ic + 1, (ic + 1) & 1);   // overlaps compute(ic)

        const uint32_t st = sbase + (ic & 1) * STAGE_B;
#pragma unroll
        for (int kk = 0; kk < 2; kk++) {
            const uint32_t colb = (uint32_t)(kk * 16 + lhalf * 8) * 2;
            uint32_t ah[4][4], al[4][4];
#pragma unroll
            for (int i = 0; i < 4; i++) {
                uint32_t ra = st + (uint32_t)((wm * 64 + i * 16 + lr16) * 40) * 2 + colb;
                ldsm4(ah[i], ra);
                ldsm4(al[i], ra + ARR_B);
            }
            uint32_t bh[2][4], bl[2][4];
#pragma unroll
            for (int jp = 0; jp < 2; jp++) {
                uint32_t rb = st + 2*ARR_B + (uint32_t)((wn * 32 + jp * 16 + lr16) * 40) * 2 + colb;
                ldsm4(bh[jp], rb);
                ldsm4(bl[jp], rb + ARR_B);
            }
#pragma unroll
            for (int i = 0; i < 4; i++)
#pragma unroll
                for (int j = 0; j < 4; j++) {
                    const int jp = j >> 1, jo = j & 1;
                    uint32_t bj_h[2] = { bh[jp][jo], bh[jp][jo + 2] };
                    uint32_t bj_l[2] = { bl[jp][jo], bl[jp][jo + 2] };
                    mma_bf16(acc[i][j], ah[i], bj_h);
                    mma_bf16(acc[i][j], ah[i], bj_l);
                    mma_bf16(acc[i][j], al[i], bj_h);
                }
        }
    }
}

// ============================================================
// Persistent QKV projection with fused RoPE/split (q,k) and
// transpose/split (v) epilogues. No fp32 round-trip.
// ============================================================
__global__ __launch_bounds__(256, 2) void mma_gemm_qkv()
{
    extern __shared__ char gsm[];
    float* eps = (float*)gsm;             // epilogue tile [128][131] fp32 (67072 B)
    const int tid = threadIdx.x, wid = tid >> 5, lane = tid & 31;
    const int wm = wid >> 2, wn = wid & 3, g = lane >> 2, kc = lane & 3;

    const int ri = tid & 63;              // rope pair index
    const float rope_inv = powf(10000.0f, -(float)(2 * ri) / 128.0f);

    for (int tile = blockIdx.x; tile < NTILES_QKV; tile += gridDim.x) {
        const int z = tile >> 9;          // 0,1,2
        const int t5 = tile & 511;
        const int n0 = (t5 & 15) * 128;
        const int m0 = (t5 >> 4) * 128;
        const __nv_bfloat16* Bhg = (z == 0) ? g_wqh : (z == 1) ? g_wkh : g_wvh;
        const __nv_bfloat16* Blg = (z == 0) ? g_wql : (z == 1) ? g_wkl : g_wvl;

        float acc[4][4][4];
#pragma unroll
        for (int i = 0; i < 4; i++)
#pragma unroll
            for (int j = 0; j < 4; j++)
#pragma unroll
                for (int r = 0; r < 4; r++) acc[i][j][r] = 0.f;

        mma_mainloop4(g_xh, g_xl, Bhg, Blg, m0, n0, gsm, acc);
        __syncthreads();                  // all warps done reading stages

        // acc -> eps[128][131]
#pragma unroll
        for (int i = 0; i < 4; i++) {
            int r0 = wm * 64 + i * 16 + g, r1 = r0 + 8;
#pragma unroll
            for (int j = 0; j < 4; j++) {
                int c = wn * 32 + j * 8 + kc * 2;
                eps[r0 * 131 + c]     = acc[i][j][0];
                eps[r0 * 131 + c + 1] = acc[i][j][1];
                eps[r1 * 131 + c]     = acc[i][j][2];
                eps[r1 * 131 + c + 1] = acc[i][j][3];
            }
        }
        __syncthreads();

        const int b = m0 >> 11;
        const int h = n0 >> 7;
        if (z < 2) {
            // RoPE + split -> [bh][t][d]
            __nv_bfloat16* dh = ((z == 0) ? g_qh : g_kh) + (size_t)(b * HH + h) * TT * DD;
            __nv_bfloat16* dl = ((z == 0) ? g_ql : g_kl) + (size_t)(b * HH + h) * TT * DD;
            const int rg = tid >> 6;      // 0..3
#pragma unroll 4
            for (int rr = 0; rr < 32; rr++) {
                int r = rg * 32 + rr;
                int t = (m0 + r) & 2047;
                float ang = (float)t * rope_inv;
                float s_, c_;
                sincosf(ang, &s_, &c_);
                float x1 = eps[r * 131 + ri];
                float x2 = eps[r * 131 + ri + 64];
                float v1 = x1 * c_ - x2 * s_;
                float v2 = x2 * c_ + x1 * s_;
                size_t base = (size_t)t * DD + ri;
                __nv_bfloat16 h1 = __float2bfloat16_rn(v1);
                dh[base] = h1;
                dl[base] = __float2bfloat16_rn(v1 - __bfloat162float(h1));
                __nv_bfloat16 h2 = __float2bfloat16_rn(v2);
                dh[base + 64] = h2;
                dl[base + 64] = __float2bfloat16_rn(v2 - __bfloat162float(h2));
            }
        } else {
            // transpose + split -> [bh][d][t]
            __nv_bfloat16* dh = g_vth + (size_t)(b * HH + h) * DD * TT;
            __nv_bfloat16* dl = g_vtl + (size_t)(b * HH + h) * DD * TT;
            const int d  = tid & 127;
            const int th = (tid >> 7) * 64;
            const int trow = m0 & 2047;
#pragma unroll
            for (int u = 0; u < 64; u += 8) {
                __nv_bfloat16 hv[8], lv[8];
#pragma unroll
                for (int w = 0; w < 8; w++) {
                    float v = eps[(th + u + w) * 131 + d];
                    __nv_bfloat16 hh = __float2bfloat16_rn(v);
                    hv[w] = hh;
                    lv[w] = __float2bfloat16_rn(v - __bfloat162float(hh));
                }
                *(uint4*)&dh[(size_t)d * TT + trow + th + u] = *(uint4*)hv;
                *(uint4*)&dl[(size_t)d * TT + trow + th + u] = *(uint4*)lv;
            }
        }
        __syncthreads();                  // eps free before next tile's cp.async
    }
}

// ============================================================
// Persistent output projection: out = attn(hi/lo) @ Wo^T -> fp32
// ============================================================
__global__ __launch_bounds__(256, 2) void mma_gemm_out(float* __restrict__ out)
{
    extern __shared__ char gsm[];
    const int tid = threadIdx.x, wid = tid >> 5, lane = tid & 31;
    const int wm = wid >> 2, wn = wid & 3, g = lane >> 2, kc = lane & 3;

    for (int tile = blockIdx.x; tile < NTILES_OUT; tile += gridDim.x) {
        const int n0 = (tile & 15) * 128;
        const int m0 = (tile >> 4) * 128;

        float acc[4][4][4];
#pragma unroll
        for (int i = 0; i < 4; i++)
#pragma unroll
            for (int j = 0; j < 4; j++)
#pragma unroll
                for (int r = 0; r < 4; r++) acc[i][j][r] = 0.f;

        mma_mainloop4(g_ah, g_al, g_woh, g_wol, m0, n0, gsm, acc);

#pragma unroll
        for (int i = 0; i < 4; i++) {
            int m = m0 + wm * 64 + i * 16 + g;
            float* d0 = out + (size_t)m * CC + n0;
            float* d1 = out + (size_t)(m + 8) * CC + n0;
#pragma unroll
            for (int j = 0; j < 4; j++) {
                int c = wn * 32 + j * 8 + kc * 2;
                d0[c]     = acc[i][j][0];
                d0[c + 1] = acc[i][j][1];
                d1[c]     = acc[i][j][2];
                d1[c + 1] = acc[i][j][3];
            }
        }
        __syncthreads();   // all warps past stage reads before next tile's issue
    }
}

// ============================================================
// Tensor-core flash attention, cp.async double-buffered K/V.
// Linear grid, descending-cost schedule.
// ============================================================
#define AQH 0
#define AQL 17408
#define ASTG 34816
#define ASTRIDE 35840
#define ATT_SMEM_BF16 (ASTG + 2*ASTRIDE)   // 106496
#define ATT_SMEM_BYTES (ATT_SMEM_BF16 * 2) // 212992

__global__ __launch_bounds__(256) void attn_mma_kernel()
{
    extern __shared__ __nv_bfloat16 sm[];
    __nv_bfloat16* sQh = sm + AQH;   // [128][136]
    __nv_bfloat16* sQl = sm + AQL;

    const int tid = threadIdx.x;
    const int wid = tid >> 5;
    const int lane = tid & 31;
    const int g  = lane >> 2;
    const int kc = lane & 3;
    const int bid = blockIdx.x;
    const int qt = (TT / 128 - 1) - (bid >> 5);   // big tiles first
    const int bh = bid & 31;
    const int q0 = qt * 128;

    const __nv_bfloat16* Qhg = g_qh + ((size_t)bh * TT + q0) * DD;
    const __nv_bfloat16* Qlg = g_ql + ((size_t)bh * TT + q0) * DD;
    const __nv_bfloat16* Khg = g_kh + (size_t)bh * TT * DD;
    const __nv_bfloat16* Klg = g_kl + (size_t)bh * TT * DD;
    const __nv_bfloat16* Vhg = g_vth + (size_t)bh * DD * TT;
    const __nv_bfloat16* Vlg = g_vtl + (size_t)bh * DD * TT;

    const uint32_t smb = smem_u32(sm);

    // load Q tile (128 x 128)
    for (int f = tid; f < 2048; f += 256) {
        int row = f >> 4, seg = (f & 15) * 8;
        *(uint4*)&sQh[row * 136 + seg] = *(const uint4*)&Qhg[row * DD + seg];
        *(uint4*)&sQl[row * 136 + seg] = *(const uint4*)&Qlg[row * DD + seg];
    }

    const uint32_t* q32h = (const uint32_t*)sQh;
    const uint32_t* q32l = (const uint32_t*)sQl;

    auto issue_kv = [&](int kt, int s) {
        const int k0 = kt * 64;
        uint32_t stb = smb + (uint32_t)(ASTG + s * ASTRIDE) * 2;
#pragma unroll
        for (int it = 0; it < 4; it++) {
            int f = tid + it * 256;
            int row = f >> 4, seg = (f & 15) * 8;
            uint32_t so = (uint32_t)(row * 136 + seg) * 2;
            CP_ASYNC16(stb + so,            Khg + (size_t)(k0 + row) * DD + seg);
            CP_ASYNC16(stb + 8704*2 + so,   Klg + (size_t)(k0 + row) * DD + seg);
        }
#pragma unroll
        for (int it = 0; it < 4; it++) {
            int f = tid + it * 256;
            int row = f >> 3, seg = (f & 7) * 8;
            uint32_t so = (uint32_t)(row * 72 + seg) * 2;
            CP_ASYNC16(stb + 17408*2 + so,  Vhg + (size_t)row * TT + k0 + seg);
            CP_ASYNC16(stb + 26624*2 + so,  Vlg + (size_t)row * TT + k0 + seg);
        }
        CP_COMMIT();
    };

    float o[16][4];
#pragma unroll
    for (int n = 0; n < 16; n++)
#pragma unroll
        for (int e = 0; e < 4; e++) o[n][e] = 0.f;
    float m0 = -INFINITY, m1 = -INFINITY, l0 = 0.f, l1 = 0.f;
    const float scale = 0.088388347648318447f;   // 1/sqrt(128)
    const int rq = wid * 16;

    const int nkt = 2 * qt + 2;     // cover keys [0, q0+128)
    issue_kv(0, 0);
    for (int kt = 0; kt < nkt; kt++) {
        const int k0 = kt * 64;
        if (kt) __syncthreads();                 // stage (kt+1)&1 free
        if (kt + 1 < nkt) { issue_kv(kt + 1, (kt + 1) & 1); CP_WAIT1(); }
        else              { CP_WAIT0(); }
        __syncthreads();                          // tile kt visible (and Q on kt==0)

        const uint32_t* k32h = (const uint32_t*)(sm + ASTG + (kt & 1) * ASTRIDE);
        const uint32_t* k32l = k32h + 4352;
        const uint32_t* v32h = k32h + 8704;
        const uint32_t* v32l = k32h + 13312;

        // ---- S = Q K^T (bf16x3) ----
        float s[8][4];
#pragma unroll
        for (int j = 0; j < 8; j++)
#pragma unroll
            for (int e = 0; e < 4; e++) s[j][e] = 0.f;

#pragma unroll
        for (int ks = 0; ks < 8; ks++) {
            const int c = ks * 8 + kc;
            uint32_t ah[4], al[4];
            ah[0] = q32h[(rq + g) * 68 + c];
            ah[1] = q32h[(rq + g + 8) * 68 + c];
            ah[2] = q32h[(rq + g) * 68 + c + 4];
            ah[3] = q32h[(rq + g + 8) * 68 + c + 4];
            al[0] = q32l[(rq + g) * 68 + c];
            al[1] = q32l[(rq + g + 8) * 68 + c];
            al[2] = q32l[(rq + g) * 68 + c + 4];
            al[3] = q32l[(rq + g + 8) * 68 + c + 4];
#pragma unroll
            for (int j = 0; j < 8; j++) {
                int rn = (j * 8 + g) * 68 + c;
                uint32_t kb[2], kl2[2];
                kb[0]  = k32h[rn]; kb[1]  = k32h[rn + 4];
                kl2[0] = k32l[rn]; kl2[1] = k32l[rn + 4];
                mma_bf16(s[j], ah, kb);
                mma_bf16(s[j], ah, kl2);
                mma_bf16(s[j], al, kb);
            }
        }

        // scale + causal mask (only on the two diagonal tiles)
        const int row0 = q0 + rq + g;
        const int row1 = row0 + 8;
#pragma unroll
        for (int j = 0; j < 8; j++)
#pragma unroll
            for (int e = 0; e < 4; e++) s[j][e] *= scale;
        if (kt >= 2 * qt) {
#pragma unroll
            for (int j = 0; j < 8; j++) {
                int cb = k0 + j * 8 + kc * 2;
                if (cb     > row0) s[j][0] = -INFINITY;
                if (cb + 1 > row0) s[j][1] = -INFINITY;
                if (cb     > row1) s[j][2] = -INFINITY;
                if (cb + 1 > row1) s[j][3] = -INFINITY;
            }
        }

        // ---- online softmax ----
        float mx0 = -INFINITY, mx1 = -INFINITY;
#pragma unroll
        for (int j = 0; j < 8; j++) {
            mx0 = fmaxf(mx0, fmaxf(s[j][0], s[j][1]));
            mx1 = fmaxf(mx1, fmaxf(s[j][2], s[j][3]));
        }
        mx0 = fmaxf(mx0, __shfl_xor_sync(0xffffffffu, mx0, 1));
        mx0 = fmaxf(mx0, __shfl_xor_sync(0xffffffffu, mx0, 2));
        mx1 = fmaxf(mx1, __shfl_xor_sync(0xffffffffu, mx1, 1));
        mx1 = fmaxf(mx1, __shfl_xor_sync(0xffffffffu, mx1, 2));
        float mn0 = fmaxf(m0, mx0), mn1 = fmaxf(m1, mx1);
        float r0 = __expf(m0 - mn0), r1 = __expf(m1 - mn1);
        float sum0 = 0.f, sum1 = 0.f;
#pragma unroll
        for (int j = 0; j < 8; j++) {
            s[j][0] = __expf(s[j][0] - mn0); sum0 += s[j][0];
            s[j][1] = __expf(s[j][1] - mn0); sum0 += s[j][1];
            s[j][2] = __expf(s[j][2] - mn1); sum1 += s[j][2];
            s[j][3] = __expf(s[j][3] - mn1); sum1 += s[j][3];
        }
        sum0 += __shfl_xor_sync(0xffffffffu, sum0, 1);
        sum0 += __shfl_xor_sync(0xffffffffu, sum0, 2);
        sum1 += __shfl_xor_sync(0xffffffffu, sum1, 1);
        sum1 += __shfl_xor_sync(0xffffffffu, sum1, 2);
        l0 = l0 * r0 + sum0;  m0 = mn0;
        l1 = l1 * r1 + sum1;  m1 = mn1;
#pragma unroll
        for (int n = 0; n < 16; n++) {
            o[n][0] *= r0; o[n][1] *= r0;
            o[n][2] *= r1; o[n][3] *= r1;
        }

        // ---- O += P V (bf16x3) ----
#pragma unroll
        for (int ks2 = 0; ks2 < 4; ks2++) {
            const int j0 = ks2 * 2, j1 = j0 + 1;
            uint32_t ph[4], pl[4];
            split2(s[j0][0], s[j0][1], ph[0], pl[0]);
            split2(s[j0][2], s[j0][3], ph[1], pl[1]);
            split2(s[j1][0], s[j1][1], ph[2], pl[2]);
            split2(s[j1][2], s[j1][3], ph[3], pl[3]);
            const int c = ks2 * 8 + kc;
#pragma unroll
            for (int nd = 0; nd < 16; nd++) {
                int rv = (nd * 8 + g) * 36 + c;
                uint32_t vb[2], vl2[2];
                vb[0]  = v32h[rv]; vb[1]  = v32h[rv + 4];
                vl2[0] = v32l[rv]; vl2[1] = v32l[rv + 4];
                mma_bf16(o[nd], ph, vb);
                mma_bf16(o[nd], ph, vl2);
                mma_bf16(o[nd], pl, vb);
            }
        }
    }

    // ---- epilogue: normalize + split -> g_ah / g_al [B,T,C] ----
    float i0 = 1.f / l0, i1 = 1.f / l1;
    const int b = bh >> 4, h = bh & 15;
    const int t0r = q0 + rq + g;
    __nv_bfloat16* ah0 = g_ah + ((size_t)(b * TT + t0r)) * CC + h * DD;
    __nv_bfloat16* al0 = g_al + ((size_t)(b * TT + t0r)) * CC + h * DD;
    __nv_bfloat16* ah1 = g_ah + ((size_t)(b * TT + t0r + 8)) * CC + h * DD;
    __nv_bfloat16* al1 = g_al + ((size_t)(b * TT + t0r + 8)) * CC + h * DD;
#pragma unroll
    for (int nd = 0; nd < 16; nd++) {
        int cc2 = nd * 8 + kc * 2;
        uint32_t hh, ll;
        split2(o[nd][0] * i0, o[nd][1] * i0, hh, ll);
        *(uint32_t*)&ah0[cc2] = hh;
        *(uint32_t*)&al0[cc2] = ll;
        split2(o[nd][2] * i1, o[nd][3] * i1, hh, ll);
        *(uint32_t*)&ah1[cc2] = hh;
        *(uint32_t*)&al1[cc2] = ll;
    }
}

// ============================================================
extern "C" void kernel_launch(void* const* d_in, const int* in_sizes, int n_in,
                              void* d_out, int out_size)
{
    const float* x  = (const float*)d_in[0];
    const float* Wq = (const float*)d_in[1];
    const float* Wk = (const float*)d_in[2];
    const float* Wv = (const float*)d_in[3];
    const float* Wo = (const float*)d_in[4];
    float* out = (float*)d_out;

    cudaFuncSetAttribute(attn_mma_kernel, cudaFuncAttributeMaxDynamicSharedMemorySize,
                         ATT_SMEM_BYTES);
    cudaFuncSetAttribute(mma_gemm_qkv, cudaFuncAttributeMaxDynamicSharedMemorySize,
                         GEMM_SMEM2);
    cudaFuncSetAttribute(mma_gemm_out, cudaFuncAttributeMaxDynamicSharedMemorySize,
                         GEMM_SMEM2);

    // 0) fused pre-split of x + all weights (one launch)
    split_all<<<24576, 256>>>(x, Wq, Wk, Wv, Wo);

    // 1) persistent QKV projections (128x128, 2 CTA/SM) + fused RoPE/V-transpose
    mma_gemm_qkv<<<NGEMM_CTAS, 256, GEMM_SMEM2>>>();

    // 2) tensor-core causal flash attention (descending-cost schedule)
    attn_mma_kernel<<<(TT / 128) * BH, 256, ATT_SMEM_BYTES>>>();

    // 3) persistent output projection (128x128, 2 CTA/SM) -> fp32 out
    mma_gemm_out<<<NGEMM_CTAS, 256, GEMM_SMEM2>>>(out);
}

// round 14
// speedup vs baseline: 1.0438x; 1.0004x over previous
#include <cuda_runtime.h>
#include <cuda_bf16.h>
#include <math.h>
#include <stdint.h>

#define BB    2
#define TT    2048
#define CC    2048
#define HH    16
#define DD    128
#define MM    (BB*TT)          // 4096 token rows
#define BH    (BB*HH)          // 32

#define KC    32               // GEMM K per chunk
#define NCHUNK (CC/KC)         // 64

// GEMM smem: per stage 4 arrays of [128][40] bf16 = 10240 B each
#define ARR_B   10240
#define STAGE_B (4*ARR_B)      // 40960
#define GEMM_SMEM2 (2*STAGE_B) // 81920 -> 2 CTAs/SM

#define NGEMM_CTAS 296         // 2 per SM
#define NTILES_QKV 1536        // 3 weights x (32 m-tiles x 16 n-tiles)
#define NTILES_OUT 512

// ---- static device scratch (allocation-free) ----
__device__ __nv_bfloat16 g_xh[MM*CC],  g_xl[MM*CC];     // pre-split input
__device__ __nv_bfloat16 g_wqh[CC*CC], g_wql[CC*CC];
__device__ __nv_bfloat16 g_wkh[CC*CC], g_wkl[CC*CC];
__device__ __nv_bfloat16 g_wvh[CC*CC], g_wvl[CC*CC];
__device__ __nv_bfloat16 g_woh[CC*CC], g_wol[CC*CC];
__device__ __nv_bfloat16 g_qh[BH*TT*DD], g_ql[BH*TT*DD];   // roped q  [bh][t][d]
__device__ __nv_bfloat16 g_kh[BH*TT*DD], g_kl[BH*TT*DD];   // roped k  [bh][t][d]
__device__ __nv_bfloat16 g_vth[BH*DD*TT], g_vtl[BH*DD*TT]; // v transposed [bh][d][t]
__device__ __nv_bfloat16 g_ah[MM*CC],  g_al[MM*CC];        // attn out rows [B,T,C]

// ============================================================
// helpers
// ============================================================
__device__ __forceinline__ uint32_t smem_u32(const void* p) {
    uint32_t a;
    asm("{ .reg .u64 t; cvta.to.shared.u64 t, %1; cvt.u32.u64 %0, t; }" : "=r"(a) : "l"(p));
    return a;
}
__device__ __forceinline__ void mma_bf16(float* d, const uint32_t* a, const uint32_t* b) {
    asm volatile(
        "mma.sync.aligned.m16n8k16.row.col.f32.bf16.bf16.f32 "
        "{%0,%1,%2,%3}, {%4,%5,%6,%7}, {%8,%9}, {%0,%1,%2,%3};"
        : "+f"(d[0]), "+f"(d[1]), "+f"(d[2]), "+f"(d[3])
        : "r"(a[0]), "r"(a[1]), "r"(a[2]), "r"(a[3]), "r"(b[0]), "r"(b[1]));
}
__device__ __forceinline__ void ldsm4(uint32_t* r, uint32_t addr) {
    asm volatile("ldmatrix.sync.aligned.m8n8.x4.shared.b16 {%0,%1,%2,%3}, [%4];"
        : "=r"(r[0]), "=r"(r[1]), "=r"(r[2]), "=r"(r[3]) : "r"(addr));
}
#define CP_ASYNC16(dst, src) \
    asm volatile("cp.async.cg.shared.global [%0], [%1], 16;" :: "r"(dst), "l"(src))
#define CP_COMMIT() asm volatile("cp.async.commit_group;" ::: "memory")
#define CP_WAIT0()  asm volatile("cp.async.wait_group 0;" ::: "memory")
#define CP_WAIT1()  asm volatile("cp.async.wait_group 1;" ::: "memory")

__device__ __forceinline__ void split2(float a, float b, uint32_t& hi, uint32_t& lo) {
    __nv_bfloat16 ha = __float2bfloat16_rn(a);
    __nv_bfloat16 hb = __float2bfloat16_rn(b);
    float la = a - __bfloat162float(ha);
    float lb = b - __bfloat162float(hb);
    __nv_bfloat162 h; h.x = ha; h.y = hb;
    hi = *(uint32_t*)&h;
    __nv_bfloat162 l = __floats2bfloat162_rn(la, lb);
    lo = *(uint32_t*)&l;
}

// ============================================================
// fused fp32 -> bf16 hi/lo splitter (x + 4 weights, one launch)
// segments of 1M float4 groups: [x(2), Wq, Wk, Wv, Wo]
// ============================================================
__global__ __launch_bounds__(256) void split_all(
    const float* __restrict__ x,  const float* __restrict__ Wq,
    const float* __restrict__ Wk, const float* __restrict__ Wv,
    const float* __restrict__ Wo)
{
    int i = blockIdx.x * 256 + threadIdx.x;   // 0 .. 6291455
    int seg = i >> 20;
    const float* src;
    __nv_bfloat16 *h, *l;
    int off;
    if (seg < 2)      { src = x;  h = g_xh;  l = g_xl;  off = i; }
    else if (seg == 2){ src = Wq; h = g_wqh; l = g_wql; off = i - (2 << 20); }
    else if (seg == 3){ src = Wk; h = g_wkh; l = g_wkl; off = i - (3 << 20); }
    else if (seg == 4){ src = Wv; h = g_wvh; l = g_wvl; off = i - (4 << 20); }
    else              { src = Wo; h = g_woh; l = g_wol; off = i - (5 << 20); }
    float4 v = ((const float4*)src)[off];
    uint32_t h0, l0, h1, l1;
    split2(v.x, v.y, h0, l0);
    split2(v.z, v.w, h1, l1);
    uint2 hh; hh.x = h0; hh.y = h1;
    uint2 ll; ll.x = l0; ll.y = l1;
    ((uint2*)h)[off] = hh;
    ((uint2*)l)[off] = ll;
}

// ============================================================
// bf16x3 GEMM mainloop (R9-proven): 128x128 tile, 256 threads
// (8 warps 2x4), cp.async 2-stage, ldmatrix, 2 CTAs/SM.
// ============================================================
__device__ __forceinline__ void mma_mainloop4(
    const __nv_bfloat16* __restrict__ Ahg, const __nv_bfloat16* __restrict__ Alg,
    const __nv_bfloat16* __restrict__ Bhg, const __nv_bfloat16* __restrict__ Blg,
    int m0, int n0, char* gsm, float acc[4][4][4])
{
    const int tid  = threadIdx.x;
    const int wid  = tid >> 5;
    const int lane = tid & 31;
    const int wm   = wid >> 2;
    const int wn   = wid & 3;
    const int lr16 = lane & 15;
    const int lhalf = lane >> 4;

    const uint32_t sbase = smem_u32(gsm);

    const int lrow = tid >> 2;            // 0..63
    const int lseg = (tid & 3) * 8;       // 0,8,16,24 bf16

    auto issue = [&](int ic, int s) {
        uint32_t sb = sbase + s * STAGE_B;
        size_t kof = (size_t)ic * KC;
#pragma unroll
        for (int it = 0; it < 2; it++) {
            int row = lrow + it * 64;
            uint32_t so = (uint32_t)(row * 40 + lseg) * 2;
            size_t ga = (size_t)(m0 + row) * CC + kof + lseg;
            size_t gb = (size_t)(n0 + row) * CC + kof + lseg;
            CP_ASYNC16(sb + so,             Ahg + ga);
            CP_ASYNC16(sb + ARR_B + so,     Alg + ga);
            CP_ASYNC16(sb + 2*ARR_B + so,   Bhg + gb);
            CP_ASYNC16(sb + 3*ARR_B + so,   Blg + gb);
        }
        CP_COMMIT();
    };

    issue(0, 0);

    for (int ic = 0; ic < NCHUNK; ic++) {
        CP_WAIT0();            // stage ic ready (only pending group)
        __syncthreads();       // all warps done with the other stage
        if (ic + 1 < NCHUNK) issue(ic + 1, (ic + 1) & 1);   // overlaps compute(ic)

        const uint32_t st = sbase + (ic & 1) * STAGE_B;
#pragma unroll
        for (int kk = 0; kk < 2; kk++) {
            const uint32_t colb = (uint32_t)(kk * 16 + lhalf * 8) * 2;
            uint32_t ah[4][4], al[4][4];
#pragma unroll
            for (int i = 0; i < 4; i++) {
                uint32_t ra = st + (uint32_t)((wm * 64 + i * 16 + lr16) * 40) * 2 + colb;
                ldsm4(ah[i], ra);
                ldsm4(al[i], ra + ARR_B);
            }
            uint32_t bh[2][4], bl[2][4];
#pragma unroll
            for (int jp = 0; jp < 2; jp++) {
                uint32_t rb = st + 2*ARR_B + (uint32_t)((wn * 32 + jp * 16 + lr16) * 40) * 2 + colb;
                ldsm4(bh[jp], rb);
                ldsm4(bl[jp], rb + ARR_B);
            }
#pragma unroll
            for (int i = 0; i < 4; i++)
#pragma unroll
                for (int j = 0; j < 4; j++) {
                    const int jp = j >> 1, jo = j & 1;
                    uint32_t bj_h[2] = { bh[jp][jo], bh[jp][jo + 2] };
                    uint32_t bj_l[2] = { bl[jp][jo], bl[jp][jo + 2] };
                    mma_bf16(acc[i][j], ah[i], bj_h);
                    mma_bf16(acc[i][j], ah[i], bj_l);
                    mma_bf16(acc[i][j], al[i], bj_h);
                }
        }
    }
}

// ============================================================
// Persistent QKV projection with fused RoPE/split (q,k) and
// transpose/split (v) epilogues. No fp32 round-trip.
// ============================================================
__global__ __launch_bounds__(256, 2) void mma_gemm_qkv()
{
    extern __shared__ char gsm[];
    float* eps = (float*)gsm;             // epilogue tile [128][131] fp32 (67072 B)
    const int tid = threadIdx.x, wid = tid >> 5, lane = tid & 31;
    const int wm = wid >> 2, wn = wid & 3, g = lane >> 2, kc = lane & 3;

    const int ri = tid & 63;              // rope pair index
    const float rope_inv = powf(10000.0f, -(float)(2 * ri) / 128.0f);

    for (int tile = blockIdx.x; tile < NTILES_QKV; tile += gridDim.x) {
        const int z = tile >> 9;          // 0,1,2
        const int t5 = tile & 511;
        const int n0 = (t5 & 15) * 128;
        const int m0 = (t5 >> 4) * 128;
        const __nv_bfloat16* Bhg = (z == 0) ? g_wqh : (z == 1) ? g_wkh : g_wvh;
        const __nv_bfloat16* Blg = (z == 0) ? g_wql : (z == 1) ? g_wkl : g_wvl;

        float acc[4][4][4];
#pragma unroll
        for (int i = 0; i < 4; i++)
#pragma unroll
            for (int j = 0; j < 4; j++)
#pragma unroll
                for (int r = 0; r < 4; r++) acc[i][j][r] = 0.f;

        mma_mainloop4(g_xh, g_xl, Bhg, Blg, m0, n0, gsm, acc);
        __syncthreads();                  // all warps done reading stages

        // acc -> eps[128][131]
#pragma unroll
        for (int i = 0; i < 4; i++) {
            int r0 = wm * 64 + i * 16 + g, r1 = r0 + 8;
#pragma unroll
            for (int j = 0; j < 4; j++) {
                int c = wn * 32 + j * 8 + kc * 2;
                eps[r0 * 131 + c]     = acc[i][j][0];
                eps[r0 * 131 + c + 1] = acc[i][j][1];
                eps[r1 * 131 + c]     = acc[i][j][2];
                eps[r1 * 131 + c + 1] = acc[i][j][3];
            }
        }
        __syncthreads();

        const int b = m0 >> 11;
        const int h = n0 >> 7;
        if (z < 2) {
            // RoPE + split -> [bh][t][d]
            __nv_bfloat16* dh = ((z == 0) ? g_qh : g_kh) + (size_t)(b * HH + h) * TT * DD;
            __nv_bfloat16* dl = ((z == 0) ? g_ql : g_kl) + (size_t)(b * HH + h) * TT * DD;
            const int rg = tid >> 6;      // 0..3
#pragma unroll 4
            for (int rr = 0; rr < 32; rr++) {
                int r = rg * 32 + rr;
                int t = (m0 + r) & 2047;
                float ang = (float)t * rope_inv;
                float s_, c_;
                sincosf(ang, &s_, &c_);
                float x1 = eps[r * 131 + ri];
                float x2 = eps[r * 131 + ri + 64];
                float v1 = x1 * c_ - x2 * s_;
                float v2 = x2 * c_ + x1 * s_;
                size_t base = (size_t)t * DD + ri;
                __nv_bfloat16 h1 = __float2bfloat16_rn(v1);
                dh[base] = h1;
                dl[base] = __float2bfloat16_rn(v1 - __bfloat162float(h1));
                __nv_bfloat16 h2 = __float2bfloat16_rn(v2);
                dh[base + 64] = h2;
                dl[base + 64] = __float2bfloat16_rn(v2 - __bfloat162float(h2));
            }
        } else {
            // transpose + split -> [bh][d][t]
            __nv_bfloat16* dh = g_vth + (size_t)(b * HH + h) * DD * TT;
            __nv_bfloat16* dl = g_vtl + (size_t)(b * HH + h) * DD * TT;
            const int d  = tid & 127;
            const int th = (tid >> 7) * 64;
            const int trow = m0 & 2047;
#pragma unroll
            for (int u = 0; u < 64; u += 8) {
                __nv_bfloat16 hv[8], lv[8];
#pragma unroll
                for (int w = 0; w < 8; w++) {
                    float v = eps[(th + u + w) * 131 + d];
                    __nv_bfloat16 hh = __float2bfloat16_rn(v);
                    hv[w] = hh;
                    lv[w] = __float2bfloat16_rn(v - __bfloat162float(hh));
                }
                *(uint4*)&dh[(size_t)d * TT + trow + th + u] = *(uint4*)hv;
                *(uint4*)&dl[(size_t)d * TT + trow + th + u] = *(uint4*)lv;
            }
        }
        __syncthreads();                  // eps free before next tile's cp.async
    }
}

// ============================================================
// Persistent output projection: out = attn(hi/lo) @ Wo^T -> fp32
// ============================================================
__global__ __launch_bounds__(256, 2) void mma_gemm_out(float* __restrict__ out)
{
    extern __shared__ char gsm[];
    const int tid = threadIdx.x, wid = tid >> 5, lane = tid & 31;
    const int wm = wid >> 2, wn = wid & 3, g = lane >> 2, kc = lane & 3;

    for (int tile = blockIdx.x; tile < NTILES_OUT; tile += gridDim.x) {
        const int n0 = (tile & 15) * 128;
        const int m0 = (tile >> 4) * 128;

        float acc[4][4][4];
#pragma unroll
        for (int i = 0; i < 4; i++)
#pragma unroll
            for (int j = 0; j < 4; j++)
#pragma unroll
                for (int r = 0; r < 4; r++) acc[i][j][r] = 0.f;

        mma_mainloop4(g_ah, g_al, g_woh, g_wol, m0, n0, gsm, acc);

#pragma unroll
        for (int i = 0; i < 4; i++) {
            int m = m0 + wm * 64 + i * 16 + g;
            float* d0 = out + (size_t)m * CC + n0;
            float* d1 = out + (size_t)(m + 8) * CC + n0;
#pragma unroll
            for (int j = 0; j < 4; j++) {
                int c = wn * 32 + j * 8 + kc * 2;
                d0[c]     = acc[i][j][0];
                d0[c + 1] = acc[i][j][1];
                d1[c]     = acc[i][j][2];
                d1[c + 1] = acc[i][j][3];
            }
        }
        __syncthreads();   // all warps past stage reads before next tile's issue
    }
}

// ============================================================
// Tensor-core flash attention, cp.async double-buffered K/V.
// Linear grid, descending-cost schedule.
// ============================================================
#define AQH 0
#define AQL 17408
#define ASTG 34816
#define ASTRIDE 35840
#define ATT_SMEM_BF16 (ASTG + 2*ASTRIDE)   // 106496
#define ATT_SMEM_BYTES (ATT_SMEM_BF16 * 2) // 212992

__global__ __launch_bounds__(256) void attn_mma_kernel()
{
    extern __shared__ __nv_bfloat16 sm[];
    __nv_bfloat16* sQh = sm + AQH;   // [128][136]
    __nv_bfloat16* sQl = sm + AQL;

    const int tid = threadIdx.x;
    const int wid = tid >> 5;
    const int lane = tid & 31;
    const int g  = lane >> 2;
    const int kc = lane & 3;
    const int bid = blockIdx.x;
    const int qt = (TT / 128 - 1) - (bid >> 5);   // big tiles first
    const int bh = bid & 31;
    const int q0 = qt * 128;

    const __nv_bfloat16* Qhg = g_qh + ((size_t)bh * TT + q0) * DD;
    const __nv_bfloat16* Qlg = g_ql + ((size_t)bh * TT + q0) * DD;
    const __nv_bfloat16* Khg = g_kh + (size_t)bh * TT * DD;
    const __nv_bfloat16* Klg = g_kl + (size_t)bh * TT * DD;
    const __nv_bfloat16* Vhg = g_vth + (size_t)bh * DD * TT;
    const __nv_bfloat16* Vlg = g_vtl + (size_t)bh * DD * TT;

    const uint32_t smb = smem_u32(sm);

    // load Q tile (128 x 128)
    for (int f = tid; f < 2048; f += 256) {
        int row = f >> 4, seg = (f & 15) * 8;
        *(uint4*)&sQh[row * 136 + seg] = *(const uint4*)&Qhg[row * DD + seg];
        *(uint4*)&sQl[row * 136 + seg] = *(const uint4*)&Qlg[row * DD + seg];
    }

    const uint32_t* q32h = (const uint32_t*)sQh;
    const uint32_t* q32l = (const uint32_t*)sQl;

    auto issue_kv = [&](int kt, int s) {
        const int k0 = kt * 64;
        uint32_t stb = smb + (uint32_t)(ASTG + s * ASTRIDE) * 2;
#pragma unroll
        for (int it = 0; it < 4; it++) {
            int f = tid + it * 256;
            int row = f >> 4, seg = (f & 15) * 8;
            uint32_t so = (uint32_t)(row * 136 + seg) * 2;
            CP_ASYNC16(stb + so,            Khg + (size_t)(k0 + row) * DD + seg);
            CP_ASYNC16(stb + 8704*2 + so,   Klg + (size_t)(k0 + row) * DD + seg);
        }
#pragma unroll
        for (int it = 0; it < 4; it++) {
            int f = tid + it * 256;
            int row = f >> 3, seg = (f & 7) * 8;
            uint32_t so = (uint32_t)(row * 72 + seg) * 2;
            CP_ASYNC16(stb + 17408*2 + so,  Vhg + (size_t)row * TT + k0 + seg);
            CP_ASYNC16(stb + 26624*2 + so,  Vlg + (size_t)row * TT + k0 + seg);
        }
        CP_COMMIT();
    };

    float o[16][4];
#pragma unroll
    for (int n = 0; n < 16; n++)
#pragma unroll
        for (int e = 0; e < 4; e++) o[n][e] = 0.f;
    float m0 = -INFINITY, m1 = -INFINITY, l0 = 0.f, l1 = 0.f;
    const float scale = 0.088388347648318447f;   // 1/sqrt(128)
    const int rq = wid * 16;

    const int nkt = 2 * qt + 2;     // cover keys [0, q0+128)
    issue_kv(0, 0);
    for (int kt = 0; kt < nkt; kt++) {
        const int k0 = kt * 64;
        if (kt) __syncthreads();                 // stage (kt+1)&1 free
        if (kt + 1 < nkt) { issue_kv(kt + 1, (kt + 1) & 1); CP_WAIT1(); }
        else              { CP_WAIT0(); }
        __syncthreads();                          // tile kt visible (and Q on kt==0)

        const uint32_t* k32h = (const uint32_t*)(sm + ASTG + (kt & 1) * ASTRIDE);
        const uint32_t* k32l = k32h + 4352;
        const uint32_t* v32h = k32h + 8704;
        const uint32_t* v32l = k32h + 13312;

        // ---- S = Q K^T (bf16x3) ----
        float s[8][4];
#pragma unroll
        for (int j = 0; j < 8; j++)
#pragma unroll
            for (int e = 0; e < 4; e++) s[j][e] = 0.f;

#pragma unroll
        for (int ks = 0; ks < 8; ks++) {
            const int c = ks * 8 + kc;
            uint32_t ah[4], al[4];
            ah[0] = q32h[(rq + g) * 68 + c];
            ah[1] = q32h[(rq + g + 8) * 68 + c];
            ah[2] = q32h[(rq + g) * 68 + c + 4];
            ah[3] = q32h[(rq + g + 8) * 68 + c + 4];
            al[0] = q32l[(rq + g) * 68 + c];
            al[1] = q32l[(rq + g + 8) * 68 + c];
            al[2] = q32l[(rq + g) * 68 + c + 4];
            al[3] = q32l[(rq + g + 8) * 68 + c + 4];
#pragma unroll
            for (int j = 0; j < 8; j++) {
                int rn = (j * 8 + g) * 68 + c;
                uint32_t kb[2], kl2[2];
                kb[0]  = k32h[rn]; kb[1]  = k32h[rn + 4];
                kl2[0] = k32l[rn]; kl2[1] = k32l[rn + 4];
                mma_bf16(s[j], ah, kb);
                mma_bf16(s[j], ah, kl2);
                mma_bf16(s[j], al, kb);
            }
        }

        // scale + causal mask (only on the two diagonal tiles)
        const int row0 = q0 + rq + g;
        const int row1 = row0 + 8;
#pragma unroll
        for (int j = 0; j < 8; j++)
#pragma unroll
            for (int e = 0; e < 4; e++) s[j][e] *= scale;
        if (kt >= 2 * qt) {
#pragma unroll
            for (int j = 0; j < 8; j++) {
                int cb = k0 + j * 8 + kc * 2;
                if (cb     > row0) s[j][0] = -INFINITY;
                if (cb + 1 > row0) s[j][1] = -INFINITY;
                if (cb     > row1) s[j][2] = -INFINITY;
                if (cb + 1 > row1) s[j][3] = -INFINITY;
            }
        }

        // ---- online softmax ----
        float mx0 = -INFINITY, mx1 = -INFINITY;
#pragma unroll
        for (int j = 0; j < 8; j++) {
            mx0 = fmaxf(mx0, fmaxf(s[j][0], s[j][1]));
            mx1 = fmaxf(mx1, fmaxf(s[j][2], s[j][3]));
        }
        mx0 = fmaxf(mx0, __shfl_xor_sync(0xffffffffu, mx0, 1));
        mx0 = fmaxf(mx0, __shfl_xor_sync(0xffffffffu, mx0, 2));
        mx1 = fmaxf(mx1, __shfl_xor_sync(0xffffffffu, mx1, 1));
        mx1 = fmaxf(mx1, __shfl_xor_sync(0xffffffffu, mx1, 2));
        float mn0 = fmaxf(m0, mx0), mn1 = fmaxf(m1, mx1);
        float r0 = __expf(m0 - mn0), r1 = __expf(m1 - mn1);
        float sum0 = 0.f, sum1 = 0.f;
#pragma unroll
        for (int j = 0; j < 8; j++) {
            s[j][0] = __expf(s[j][0] - mn0); sum0 += s[j][0];
            s[j][1] = __expf(s[j][1] - mn0); sum0 += s[j][1];
            s[j][2] = __expf(s[j][2] - mn1); sum1 += s[j][2];
            s[j][3] = __expf(s[j][3] - mn1); sum1 += s[j][3];
        }
        sum0 += __shfl_xor_sync(0xffffffffu, sum0, 1);
        sum0 += __shfl_xor_sync(0xffffffffu, sum0, 2);
        sum1 += __shfl_xor_sync(0xffffffffu, sum1, 1);
        sum1 += __shfl_xor_sync(0xffffffffu, sum1, 2);
        l0 = l0 * r0 + sum0;  m0 = mn0;
        l1 = l1 * r1 + sum1;  m1 = mn1;
#pragma unroll
        for (int n = 0; n < 16; n++) {
            o[n][0] *= r0; o[n][1] *= r0;
            o[n][2] *= r1; o[n][3] *= r1;
        }

        // ---- O += P V (bf16x3) ----
#pragma unroll
        for (int ks2 = 0; ks2 < 4; ks2++) {
            const int j0 = ks2 * 2, j1 = j0 + 1;
            uint32_t ph[4], pl[4];
            split2(s[j0][0], s[j0][1], ph[0], pl[0]);
            split2(s[j0][2], s[j0][3], ph[1], pl[1]);
            split2(s[j1][0], s[j1][1], ph[2], pl[2]);
            split2(s[j1][2], s[j1][3], ph[3], pl[3]);
            const int c = ks2 * 8 + kc;
#pragma unroll
            for (int nd = 0; nd < 16; nd++) {
                int rv = (nd * 8 + g) * 36 + c;
                uint32_t vb[2], vl2[2];
                vb[0]  = v32h[rv]; vb[1]  = v32h[rv + 4];
                vl2[0] = v32l[rv]; vl2[1] = v32l[rv + 4];
                mma_bf16(o[nd], ph, vb);
                mma_bf16(o[nd], ph, vl2);
                mma_bf16(o[nd], pl, vb);
            }
        }
    }

    // ---- epilogue: normalize + split -> g_ah / g_al [B,T,C] ----
    float i0 = 1.f / l0, i1 = 1.f / l1;
    const int b = bh >> 4, h = bh & 15;
    const int t0r = q0 + rq + g;
    __nv_bfloat16* ah0 = g_ah + ((size_t)(b * TT + t0r)) * CC + h * DD;
    __nv_bfloat16* al0 = g_al + ((size_t)(b * TT + t0r)) * CC + h * DD;
    __nv_bfloat16* ah1 = g_ah + ((size_t)(b * TT + t0r + 8)) * CC + h * DD;
    __nv_bfloat16* al1 = g_al + ((size_t)(b * TT + t0r + 8)) * CC + h * DD;
#pragma unroll
    for (int nd = 0; nd < 16; nd++) {
        int cc2 = nd * 8 + kc * 2;
        uint32_t hh, ll;
        split2(o[nd][0] * i0, o[nd][1] * i0, hh, ll);
        *(uint32_t*)&ah0[cc2] = hh;
        *(uint32_t*)&al0[cc2] = ll;
        split2(o[nd][2] * i1, o[nd][3] * i1, hh, ll);
        *(uint32_t*)&ah1[cc2] = hh;
        *(uint32_t*)&al1[cc2] = ll;
    }
}

// ============================================================
extern "C" void kernel_launch(void* const* d_in, const int* in_sizes, int n_in,
                              void* d_out, int out_size)
{
    const float* x  = (const float*)d_in[0];
    const float* Wq = (const float*)d_in[1];
    const float* Wk = (const float*)d_in[2];
    const float* Wv = (const float*)d_in[3];
    const float* Wo = (const float*)d_in[4];
    float* out = (float*)d_out;

    cudaFuncSetAttribute(attn_mma_kernel, cudaFuncAttributeMaxDynamicSharedMemorySize,
                         ATT_SMEM_BYTES);
    cudaFuncSetAttribute(mma_gemm_qkv, cudaFuncAttributeMaxDynamicSharedMemorySize,
                         GEMM_SMEM2);
    cudaFuncSetAttribute(mma_gemm_out, cudaFuncAttributeMaxDynamicSharedMemorySize,
                         GEMM_SMEM2);

    // 0) fused pre-split of x + all weights (one launch)
    split_all<<<24576, 256>>>(x, Wq, Wk, Wv, Wo);

    // 1) persistent QKV projections (128x128, 2 CTA/SM) + fused RoPE/V-transpose
    mma_gemm_qkv<<<NGEMM_CTAS, 256, GEMM_SMEM2>>>();

    // 2) tensor-core causal flash attention (descending-cost schedule)
    attn_mma_kernel<<<(TT / 128) * BH, 256, ATT_SMEM_BYTES>>>();

    // 3) persistent output projection (128x128, 2 CTA/SM) -> fp32 out
    mma_gemm_out<<<NGEMM_CTAS, 256, GEMM_SMEM2>>>(out);
}

// round 15
// speedup vs baseline: 1.0449x; 1.0011x over previous
#include <cuda_runtime.h>
#include <cuda_bf16.h>
#include <math.h>
#include <stdint.h>

#define BB    2
#define TT    2048
#define CC    2048
#define HH    16
#define DD    128
#define MM    (BB*TT)          // 4096 token rows
#define BH    (BB*HH)          // 32

#define KC    32               // GEMM K per chunk
#define NCHUNK (CC/KC)         // 64

// GEMM smem: per stage 4 arrays of [128][40] bf16 = 10240 B each
#define ARR_B   10240
#define STAGE_B (4*ARR_B)      // 40960
#define GEMM_SMEM2 (2*STAGE_B) // 81920 -> 2 CTAs/SM

#define NGEMM_CTAS 296         // 2 per SM
#define NTILES_QKV 1536        // 3 weights x (32 m-tiles x 16 n-tiles)
#define NTILES_OUT 512

// ---- static device scratch (allocation-free) ----
__device__ __nv_bfloat16 g_xh[MM*CC],  g_xl[MM*CC];     // pre-split input
__device__ __nv_bfloat16 g_wqh[CC*CC], g_wql[CC*CC];
__device__ __nv_bfloat16 g_wkh[CC*CC], g_wkl[CC*CC];
__device__ __nv_bfloat16 g_wvh[CC*CC], g_wvl[CC*CC];
__device__ __nv_bfloat16 g_woh[CC*CC], g_wol[CC*CC];
__device__ __nv_bfloat16 g_qh[BH*TT*DD], g_ql[BH*TT*DD];   // roped q  [bh][t][d]
__device__ __nv_bfloat16 g_kh[BH*TT*DD], g_kl[BH*TT*DD];   // roped k  [bh][t][d]
__device__ __nv_bfloat16 g_vth[BH*DD*TT], g_vtl[BH*DD*TT]; // v transposed [bh][d][t]
__device__ __nv_bfloat16 g_ah[MM*CC],  g_al[MM*CC];        // attn out rows [B,T,C]

// ============================================================
// helpers
// ============================================================
__device__ __forceinline__ uint32_t smem_u32(const void* p) {
    uint32_t a;
    asm("{ .reg .u64 t; cvta.to.shared.u64 t, %1; cvt.u32.u64 %0, t; }" : "=r"(a) : "l"(p));
    return a;
}
__device__ __forceinline__ void mma_bf16(float* d, const uint32_t* a, const uint32_t* b) {
    asm volatile(
        "mma.sync.aligned.m16n8k16.row.col.f32.bf16.bf16.f32 "
        "{%0,%1,%2,%3}, {%4,%5,%6,%7}, {%8,%9}, {%0,%1,%2,%3};"
        : "+f"(d[0]), "+f"(d[1]), "+f"(d[2]), "+f"(d[3])
        : "r"(a[0]), "r"(a[1]), "r"(a[2]), "r"(a[3]), "r"(b[0]), "r"(b[1]));
}
__device__ __forceinline__ void ldsm4(uint32_t* r, uint32_t addr) {
    asm volatile("ldmatrix.sync.aligned.m8n8.x4.shared.b16 {%0,%1,%2,%3}, [%4];"
        : "=r"(r[0]), "=r"(r[1]), "=r"(r[2]), "=r"(r[3]) : "r"(addr));
}
#define CP_ASYNC16(dst, src) \
    asm volatile("cp.async.cg.shared.global [%0], [%1], 16;" :: "r"(dst), "l"(src))
#define CP_COMMIT() asm volatile("cp.async.commit_group;" ::: "memory")
#define CP_WAIT0()  asm volatile("cp.async.wait_group 0;" ::: "memory")
#define CP_WAIT1()  asm volatile("cp.async.wait_group 1;" ::: "memory")

__device__ __forceinline__ void split2(float a, float b, uint32_t& hi, uint32_t& lo) {
    __nv_bfloat16 ha = __float2bfloat16_rn(a);
    __nv_bfloat16 hb = __float2bfloat16_rn(b);
    float la = a - __bfloat162float(ha);
    float lb = b - __bfloat162float(hb);
    __nv_bfloat162 h; h.x = ha; h.y = hb;
    hi = *(uint32_t*)&h;
    __nv_bfloat162 l = __floats2bfloat162_rn(la, lb);
    lo = *(uint32_t*)&l;
}

// ============================================================
// fused fp32 -> bf16 hi/lo splitter (x + 4 weights, one launch)
// segments of 1M float4 groups: [x(2), Wq, Wk, Wv, Wo]
// ============================================================
__global__ __launch_bounds__(256) void split_all(
    const float* __restrict__ x,  const float* __restrict__ Wq,
    const float* __restrict__ Wk, const float* __restrict__ Wv,
    const float* __restrict__ Wo)
{
    int i = blockIdx.x * 256 + threadIdx.x;   // 0 .. 6291455
    int seg = i >> 20;
    const float* src;
    __nv_bfloat16 *h, *l;
    int off;
    if (seg < 2)      { src = x;  h = g_xh;  l = g_xl;  off = i; }
    else if (seg == 2){ src = Wq; h = g_wqh; l = g_wql; off = i - (2 << 20); }
    else if (seg == 3){ src = Wk; h = g_wkh; l = g_wkl; off = i - (3 << 20); }
    else if (seg == 4){ src = Wv; h = g_wvh; l = g_wvl; off = i - (4 << 20); }
    else              { src = Wo; h = g_woh; l = g_wol; off = i - (5 << 20); }
    float4 v = ((const float4*)src)[off];
    uint32_t h0, l0, h1, l1;
    split2(v.x, v.y, h0, l0);
    split2(v.z, v.w, h1, l1);
    uint2 hh; hh.x = h0; hh.y = h1;
    uint2 ll; ll.x = l0; ll.y = l1;
    ((uint2*)h)[off] = hh;
    ((uint2*)l)[off] = ll;
}

// ============================================================
// bf16x3 GEMM mainloop (R9-proven): 128x128 tile, 256 threads
// (8 warps 2x4), cp.async 2-stage, ldmatrix, 2 CTAs/SM.
// ============================================================
__device__ __forceinline__ void mma_mainloop4(
    const __nv_bfloat16* __restrict__ Ahg, const __nv_bfloat16* __restrict__ Alg,
    const __nv_bfloat16* __restrict__ Bhg, const __nv_bfloat16* __restrict__ Blg,
    int m0, int n0, char* gsm, float acc[4][4][4])
{
    const int tid  = threadIdx.x;
    const int wid  = tid >> 5;
    const int lane = tid & 31;
    const int wm   = wid >> 2;
    const int wn   = wid & 3;
    const int lr16 = lane & 15;
    const int lhalf = lane >> 4;

    const uint32_t sbase = smem_u32(gsm);

    const int lrow = tid >> 2;            // 0..63
    const int lseg = (tid & 3) * 8;       // 0,8,16,24 bf16

    auto issue = [&](int ic, int s) {
        uint32_t sb = sbase + s * STAGE_B;
        size_t kof = (size_t)ic * KC;
#pragma unroll
        for (int it = 0; it < 2; it++) {
            int row = lrow + it * 64;
            uint32_t so = (uint32_t)(row * 40 + lseg) * 2;
            size_t ga = (size_t)(m0 + row) * CC + kof + lseg;
            size_t gb = (size_t)(n0 + row) * CC + kof + lseg;
            CP_ASYNC16(sb + so,             Ahg + ga);
            CP_ASYNC16(sb + ARR_B + so,     Alg + ga);
            CP_ASYNC16(sb + 2*ARR_B + so,   Bhg + gb);
            CP_ASYNC16(sb + 3*ARR_B + so,   Blg + gb);
        }
        CP_COMMIT();
    };

    issue(0, 0);

    for (int ic = 0; ic < NCHUNK; ic++) {
        CP_WAIT0();            // stage ic ready (only pending group)
        __syncthreads();       // all warps done with the other stage
        if (ic + 1 < NCHUNK) issue(ic + 1, (ic + 1) & 1);   // overlaps compute(ic)

        const uint32_t st = sbase + (ic & 1) * STAGE_B;
#pragma unroll
        for (int kk = 0; kk < 2; kk++) {
            const uint32_t colb = (uint32_t)(kk * 16 + lhalf * 8) * 2;
            uint32_t ah[4][4], al[4][4];
#pragma unroll
            for (int i = 0; i < 4; i++) {
                uint32_t ra = st + (uint32_t)((wm * 64 + i * 16 + lr16) * 40) * 2 + colb;
                ldsm4(ah[i], ra);
                ldsm4(al[i], ra + ARR_B);
            }
            uint32_t bh[2][4], bl[2][4];
#pragma unroll
            for (int jp = 0; jp < 2; jp++) {
                uint32_t rb = st + 2*ARR_B + (uint32_t)((wn * 32 + jp * 16 + lr16) * 40) * 2 + colb;
                ldsm4(bh[jp], rb);
                ldsm4(bl[jp], rb + ARR_B);
            }
#pragma unroll
            for (int i = 0; i < 4; i++)
#pragma unroll
                for (int j = 0; j < 4; j++) {
                    const int jp = j >> 1, jo = j & 1;
                    uint32_t bj_h[2] = { bh[jp][jo], bh[jp][jo + 2] };
                    uint32_t bj_l[2] = { bl[jp][jo], bl[jp][jo + 2] };
                    mma_bf16(acc[i][j], ah[i], bj_h);
                    mma_bf16(acc[i][j], ah[i], bj_l);
                    mma_bf16(acc[i][j], al[i], bj_h);
                }
        }
    }
}

// ============================================================
// Persistent QKV projection with fused RoPE/split (q,k) and
// transpose/split (v) epilogues. No fp32 round-trip.
// ============================================================
__global__ __launch_bounds__(256, 2) void mma_gemm_qkv()
{
    extern __shared__ char gsm[];
    float* eps = (float*)gsm;             // epilogue tile [128][131] fp32 (67072 B)
    const int tid = threadIdx.x, wid = tid >> 5, lane = tid & 31;
    const int wm = wid >> 2, wn = wid & 3, g = lane >> 2, kc = lane & 3;

    const int ri = tid & 63;              // rope pair index
    const float rope_inv = powf(10000.0f, -(float)(2 * ri) / 128.0f);

    for (int tile = blockIdx.x; tile < NTILES_QKV; tile += gridDim.x) {
        const int z = tile >> 9;          // 0,1,2
        const int t5 = tile & 511;
        const int n0 = (t5 & 15) * 128;
        const int m0 = (t5 >> 4) * 128;
        const __nv_bfloat16* Bhg = (z == 0) ? g_wqh : (z == 1) ? g_wkh : g_wvh;
        const __nv_bfloat16* Blg = (z == 0) ? g_wql : (z == 1) ? g_wkl : g_wvl;

        float acc[4][4][4];
#pragma unroll
        for (int i = 0; i < 4; i++)
#pragma unroll
            for (int j = 0; j < 4; j++)
#pragma unroll
                for (int r = 0; r < 4; r++) acc[i][j][r] = 0.f;

        mma_mainloop4(g_xh, g_xl, Bhg, Blg, m0, n0, gsm, acc);
        __syncthreads();                  // all warps done reading stages

        // acc -> eps[128][131]
#pragma unroll
        for (int i = 0; i < 4; i++) {
            int r0 = wm * 64 + i * 16 + g, r1 = r0 + 8;
#pragma unroll
            for (int j = 0; j < 4; j++) {
                int c = wn * 32 + j * 8 + kc * 2;
                eps[r0 * 131 + c]     = acc[i][j][0];
                eps[r0 * 131 + c + 1] = acc[i][j][1];
                eps[r1 * 131 + c]     = acc[i][j][2];
                eps[r1 * 131 + c + 1] = acc[i][j][3];
            }
        }
        __syncthreads();

        const int b = m0 >> 11;
        const int h = n0 >> 7;
        if (z < 2) {
            // RoPE + split -> [bh][t][d]
            __nv_bfloat16* dh = ((z == 0) ? g_qh : g_kh) + (size_t)(b * HH + h) * TT * DD;
            __nv_bfloat16* dl = ((z == 0) ? g_ql : g_kl) + (size_t)(b * HH + h) * TT * DD;
            const int rg = tid >> 6;      // 0..3
#pragma unroll 4
            for (int rr = 0; rr < 32; rr++) {
                int r = rg * 32 + rr;
                int t = (m0 + r) & 2047;
                float ang = (float)t * rope_inv;
                float s_, c_;
                sincosf(ang, &s_, &c_);
                float x1 = eps[r * 131 + ri];
                float x2 = eps[r * 131 + ri + 64];
                float v1 = x1 * c_ - x2 * s_;
                float v2 = x2 * c_ + x1 * s_;
                size_t base = (size_t)t * DD + ri;
                __nv_bfloat16 h1 = __float2bfloat16_rn(v1);
                dh[base] = h1;
                dl[base] = __float2bfloat16_rn(v1 - __bfloat162float(h1));
                __nv_bfloat16 h2 = __float2bfloat16_rn(v2);
                dh[base + 64] = h2;
                dl[base + 64] = __float2bfloat16_rn(v2 - __bfloat162float(h2));
            }
        } else {
            // transpose + split -> [bh][d][t]
            __nv_bfloat16* dh = g_vth + (size_t)(b * HH + h) * DD * TT;
            __nv_bfloat16* dl = g_vtl + (size_t)(b * HH + h) * DD * TT;
            const int d  = tid & 127;
            const int th = (tid >> 7) * 64;
            const int trow = m0 & 2047;
#pragma unroll
            for (int u = 0; u < 64; u += 8) {
                __nv_bfloat16 hv[8], lv[8];
#pragma unroll
                for (int w = 0; w < 8; w++) {
                    float v = eps[(th + u + w) * 131 + d];
                    __nv_bfloat16 hh = __float2bfloat16_rn(v);
                    hv[w] = hh;
                    lv[w] = __float2bfloat16_rn(v - __bfloat162float(hh));
                }
                *(uint4*)&dh[(size_t)d * TT + trow + th + u] = *(uint4*)hv;
                *(uint4*)&dl[(size_t)d * TT + trow + th + u] = *(uint4*)lv;
            }
        }
        __syncthreads();                  // eps free before next tile's cp.async
    }
}

// ============================================================
// Persistent output projection: out = attn(hi/lo) @ Wo^T -> fp32
// ============================================================
__global__ __launch_bounds__(256, 2) void mma_gemm_out(float* __restrict__ out)
{
    extern __shared__ char gsm[];
    const int tid = threadIdx.x, wid = tid >> 5, lane = tid & 31;
    const int wm = wid >> 2, wn = wid & 3, g = lane >> 2, kc = lane & 3;

    for (int tile = blockIdx.x; tile < NTILES_OUT; tile += gridDim.x) {
        const int n0 = (tile & 15) * 128;
        const int m0 = (tile >> 4) * 128;

        float acc[4][4][4];
#pragma unroll
        for (int i = 0; i < 4; i++)
#pragma unroll
            for (int j = 0; j < 4; j++)
#pragma unroll
                for (int r = 0; r < 4; r++) acc[i][j][r] = 0.f;

        mma_mainloop4(g_ah, g_al, g_woh, g_wol, m0, n0, gsm, acc);

#pragma unroll
        for (int i = 0; i < 4; i++) {
            int m = m0 + wm * 64 + i * 16 + g;
            float* d0 = out + (size_t)m * CC + n0;
            float* d1 = out + (size_t)(m + 8) * CC + n0;
#pragma unroll
            for (int j = 0; j < 4; j++) {
                int c = wn * 32 + j * 8 + kc * 2;
                d0[c]     = acc[i][j][0];
                d0[c + 1] = acc[i][j][1];
                d1[c]     = acc[i][j][2];
                d1[c + 1] = acc[i][j][3];
            }
        }
        __syncthreads();   // all warps past stage reads before next tile's issue
    }
}

// ============================================================
// Tensor-core flash attention, cp.async double-buffered K/V.
// Linear grid, descending-cost schedule.
// ============================================================
#define AQH 0
#define AQL 17408
#define ASTG 34816
#define ASTRIDE 35840
#define ATT_SMEM_BF16 (ASTG + 2*ASTRIDE)   // 106496
#define ATT_SMEM_BYTES (ATT_SMEM_BF16 * 2) // 212992

__global__ __launch_bounds__(256) void attn_mma_kernel()
{
    extern __shared__ __nv_bfloat16 sm[];
    __nv_bfloat16* sQh = sm + AQH;   // [128][136]
    __nv_bfloat16* sQl = sm + AQL;

    const int tid = threadIdx.x;
    const int wid = tid >> 5;
    const int lane = tid & 31;
    const int g  = lane >> 2;
    const int kc = lane & 3;
    const int bid = blockIdx.x;
    const int qt = (TT / 128 - 1) - (bid >> 5);   // big tiles first
    const int bh = bid & 31;
    const int q0 = qt * 128;

    const __nv_bfloat16* Qhg = g_qh + ((size_t)bh * TT + q0) * DD;
    const __nv_bfloat16* Qlg = g_ql + ((size_t)bh * TT + q0) * DD;
    const __nv_bfloat16* Khg = g_kh + (size_t)bh * TT * DD;
    const __nv_bfloat16* Klg = g_kl + (size_t)bh * TT * DD;
    const __nv_bfloat16* Vhg = g_vth + (size_t)bh * DD * TT;
    const __nv_bfloat16* Vlg = g_vtl + (size_t)bh * DD * TT;

    const uint32_t smb = smem_u32(sm);

    // load Q tile (128 x 128)
    for (int f = tid; f < 2048; f += 256) {
        int row = f >> 4, seg = (f & 15) * 8;
        *(uint4*)&sQh[row * 136 + seg] = *(const uint4*)&Qhg[row * DD + seg];
        *(uint4*)&sQl[row * 136 + seg] = *(const uint4*)&Qlg[row * DD + seg];
    }

    const uint32_t* q32h = (const uint32_t*)sQh;
    const uint32_t* q32l = (const uint32_t*)sQl;

    auto issue_kv = [&](int kt, int s) {
        const int k0 = kt * 64;
        uint32_t stb = smb + (uint32_t)(ASTG + s * ASTRIDE) * 2;
#pragma unroll
        for (int it = 0; it < 4; it++) {
            int f = tid + it * 256;
            int row = f >> 4, seg = (f & 15) * 8;
            uint32_t so = (uint32_t)(row * 136 + seg) * 2;
            CP_ASYNC16(stb + so,            Khg + (size_t)(k0 + row) * DD + seg);
            CP_ASYNC16(stb + 8704*2 + so,   Klg + (size_t)(k0 + row) * DD + seg);
        }
#pragma unroll
        for (int it = 0; it < 4; it++) {
            int f = tid + it * 256;
            int row = f >> 3, seg = (f & 7) * 8;
            uint32_t so = (uint32_t)(row * 72 + seg) * 2;
            CP_ASYNC16(stb + 17408*2 + so,  Vhg + (size_t)row * TT + k0 + seg);
            CP_ASYNC16(stb + 26624*2 + so,  Vlg + (size_t)row * TT + k0 + seg);
        }
        CP_COMMIT();
    };

    float o[16][4];
#pragma unroll
    for (int n = 0; n < 16; n++)
#pragma unroll
        for (int e = 0; e < 4; e++) o[n][e] = 0.f;
    float m0 = -INFINITY, m1 = -INFINITY, l0 = 0.f, l1 = 0.f;
    const float scale = 0.088388347648318447f;   // 1/sqrt(128)
    const int rq = wid * 16;

    const int nkt = 2 * qt + 2;     // cover keys [0, q0+128)
    issue_kv(0, 0);
    for (int kt = 0; kt < nkt; kt++) {
        const int k0 = kt * 64;
        if (kt) __syncthreads();                 // stage (kt+1)&1 free
        if (kt + 1 < nkt) { issue_kv(kt + 1, (kt + 1) & 1); CP_WAIT1(); }
        else              { CP_WAIT0(); }
        __syncthreads();                          // tile kt visible (and Q on kt==0)

        const uint32_t* k32h = (const uint32_t*)(sm + ASTG + (kt & 1) * ASTRIDE);
        const uint32_t* k32l = k32h + 4352;
        const uint32_t* v32h = k32h + 8704;
        const uint32_t* v32l = k32h + 13312;

        // ---- S = Q K^T (bf16x3) ----
        float s[8][4];
#pragma unroll
        for (int j = 0; j < 8; j++)
#pragma unroll
            for (int e = 0; e < 4; e++) s[j][e] = 0.f;

#pragma unroll
        for (int ks = 0; ks < 8; ks++) {
            const int c = ks * 8 + kc;
            uint32_t ah[4], al[4];
            ah[0] = q32h[(rq + g) * 68 + c];
            ah[1] = q32h[(rq + g + 8) * 68 + c];
            ah[2] = q32h[(rq + g) * 68 + c + 4];
            ah[3] = q32h[(rq + g + 8) * 68 + c + 4];
            al[0] = q32l[(rq + g) * 68 + c];
            al[1] = q32l[(rq + g + 8) * 68 + c];
            al[2] = q32l[(rq + g) * 68 + c + 4];
            al[3] = q32l[(rq + g + 8) * 68 + c + 4];
#pragma unroll
            for (int j = 0; j < 8; j++) {
                int rn = (j * 8 + g) * 68 + c;
                uint32_t kb[2], kl2[2];
                kb[0]  = k32h[rn]; kb[1]  = k32h[rn + 4];
                kl2[0] = k32l[rn]; kl2[1] = k32l[rn + 4];
                mma_bf16(s[j], ah, kb);
                mma_bf16(s[j], ah, kl2);
                mma_bf16(s[j], al, kb);
            }
        }

        // scale + causal mask (only on the two diagonal tiles)
        const int row0 = q0 + rq + g;
        const int row1 = row0 + 8;
#pragma unroll
        for (int j = 0; j < 8; j++)
#pragma unroll
            for (int e = 0; e < 4; e++) s[j][e] *= scale;
        if (kt >= 2 * qt) {
#pragma unroll
            for (int j = 0; j < 8; j++) {
                int cb = k0 + j * 8 + kc * 2;
                if (cb     > row0) s[j][0] = -INFINITY;
                if (cb + 1 > row0) s[j][1] = -INFINITY;
                if (cb     > row1) s[j][2] = -INFINITY;
                if (cb + 1 > row1) s[j][3] = -INFINITY;
            }
        }

        // ---- online softmax ----
        float mx0 = -INFINITY, mx1 = -INFINITY;
#pragma unroll
        for (int j = 0; j < 8; j++) {
            mx0 = fmaxf(mx0, fmaxf(s[j][0], s[j][1]));
            mx1 = fmaxf(mx1, fmaxf(s[j][2], s[j][3]));
        }
        mx0 = fmaxf(mx0, __shfl_xor_sync(0xffffffffu, mx0, 1));
        mx0 = fmaxf(mx0, __shfl_xor_sync(0xffffffffu, mx0, 2));
        mx1 = fmaxf(mx1, __shfl_xor_sync(0xffffffffu, mx1, 1));
        mx1 = fmaxf(mx1, __shfl_xor_sync(0xffffffffu, mx1, 2));
        float mn0 = fmaxf(m0, mx0), mn1 = fmaxf(m1, mx1);
        float r0 = __expf(m0 - mn0), r1 = __expf(m1 - mn1);
        float sum0 = 0.f, sum1 = 0.f;
#pragma unroll
        for (int j = 0; j < 8; j++) {
            s[j][0] = __expf(s[j][0] - mn0); sum0 += s[j][0];
            s[j][1] = __expf(s[j][1] - mn0); sum0 += s[j][1];
            s[j][2] = __expf(s[j][2] - mn1); sum1 += s[j][2];
            s[j][3] = __expf(s[j][3] - mn1); sum1 += s[j][3];
        }
        sum0 += __shfl_xor_sync(0xffffffffu, sum0, 1);
        sum0 += __shfl_xor_sync(0xffffffffu, sum0, 2);
        sum1 += __shfl_xor_sync(0xffffffffu, sum1, 1);
        sum1 += __shfl_xor_sync(0xffffffffu, sum1, 2);
        l0 = l0 * r0 + sum0;  m0 = mn0;
        l1 = l1 * r1 + sum1;  m1 = mn1;
#pragma unroll
        for (int n = 0; n < 16; n++) {
            o[n][0] *= r0; o[n][1] *= r0;
            o[n][2] *= r1; o[n][3] *= r1;
        }

        // ---- O += P V (bf16x3) ----
#pragma unroll
        for (int ks2 = 0; ks2 < 4; ks2++) {
            const int j0 = ks2 * 2, j1 = j0 + 1;
            uint32_t ph[4], pl[4];
            split2(s[j0][0], s[j0][1], ph[0], pl[0]);
            split2(s[j0][2], s[j0][3], ph[1], pl[1]);
            split2(s[j1][0], s[j1][1], ph[2], pl[2]);
            split2(s[j1][2], s[j1][3], ph[3], pl[3]);
            const int c = ks2 * 8 + kc;
#pragma unroll
            for (int nd = 0; nd < 16; nd++) {
                int rv = (nd * 8 + g) * 36 + c;
                uint32_t vb[2], vl2[2];
                vb[0]  = v32h[rv]; vb[1]  = v32h[rv + 4];
                vl2[0] = v32l[rv]; vl2[1] = v32l[rv + 4];
                mma_bf16(o[nd], ph, vb);
                mma_bf16(o[nd], ph, vl2);
                mma_bf16(o[nd], pl, vb);
            }
        }
    }

    // ---- epilogue: normalize + split -> g_ah / g_al [B,T,C] ----
    float i0 = 1.f / l0, i1 = 1.f / l1;
    const int b = bh >> 4, h = bh & 15;
    const int t0r = q0 + rq + g;
    __nv_bfloat16* ah0 = g_ah + ((size_t)(b * TT + t0r)) * CC + h * DD;
    __nv_bfloat16* al0 = g_al + ((size_t)(b * TT + t0r)) * CC + h * DD;
    __nv_bfloat16* ah1 = g_ah + ((size_t)(b * TT + t0r + 8)) * CC + h * DD;
    __nv_bfloat16* al1 = g_al + ((size_t)(b * TT + t0r + 8)) * CC + h * DD;
#pragma unroll
    for (int nd = 0; nd < 16; nd++) {
        int cc2 = nd * 8 + kc * 2;
        uint32_t hh, ll;
        split2(o[nd][0] * i0, o[nd][1] * i0, hh, ll);
        *(uint32_t*)&ah0[cc2] = hh;
        *(uint32_t*)&al0[cc2] = ll;
        split2(o[nd][2] * i1, o[nd][3] * i1, hh, ll);
        *(uint32_t*)&ah1[cc2] = hh;
        *(uint32_t*)&al1[cc2] = ll;
    }
}

// ============================================================
extern "C" void kernel_launch(void* const* d_in, const int* in_sizes, int n_in,
                              void* d_out, int out_size)
{
    const float* x  = (const float*)d_in[0];
    const float* Wq = (const float*)d_in[1];
    const float* Wk = (const float*)d_in[2];
    const float* Wv = (const float*)d_in[3];
    const float* Wo = (const float*)d_in[4];
    float* out = (float*)d_out;

    cudaFuncSetAttribute(attn_mma_kernel, cudaFuncAttributeMaxDynamicSharedMemorySize,
                         ATT_SMEM_BYTES);
    cudaFuncSetAttribute(mma_gemm_qkv, cudaFuncAttributeMaxDynamicSharedMemorySize,
                         GEMM_SMEM2);
    cudaFuncSetAttribute(mma_gemm_out, cudaFuncAttributeMaxDynamicSharedMemorySize,
                         GEMM_SMEM2);

    // 0) fused pre-split of x + all weights (one launch)
    split_all<<<24576, 256>>>(x, Wq, Wk, Wv, Wo);

    // 1) persistent QKV projections (128x128, 2 CTA/SM) + fused RoPE/V-transpose
    mma_gemm_qkv<<<NGEMM_CTAS, 256, GEMM_SMEM2>>>();

    // 2) tensor-core causal flash attention (descending-cost schedule)
    attn_mma_kernel<<<(TT / 128) * BH, 256, ATT_SMEM_BYTES>>>();

    // 3) persistent output projection (128x128, 2 CTA/SM) -> fp32 out
    mma_gemm_out<<<NGEMM_CTAS, 256, GEMM_SMEM2>>>(out);
}